// round 13
// baseline (speedup 1.0000x reference)
#include <cuda_runtime.h>
#include <cuda_bf16.h>
#include <math.h>
#include <stdint.h>

// ---------------- problem constants ----------------
#define BB 2
#define TT 1024
#define CC 4096
#define NH 32
#define HS 128
#define ALEN 10
#define AT 1500
#define AD 1280
#define NWH 20
#define WHD 64
#define DHID 80           // AD/16
#define ATT_SCALE 0.08838834764831845f   // 1/sqrt(128)

// ---------------- fp32 scratch ----------------
__device__ float g_y   [BB*NH*TT*HS];
__device__ float g_aqkv[ALEN*3*CC];
__device__ float g_wkn [BB*AT*AD];
__device__ float g_wvn [BB*AT*AD];
__device__ float g_wk  [BB*AT*AD];
__device__ float g_wv  [BB*AT*AD];
__device__ float g_q2a [BB*NH*TT*HS];

// ---------------- bf16 hi/lo plane scratch ----------------
__device__ __nv_bfloat16 g_xh[BB*TT*CC],    g_xl[BB*TT*CC];
__device__ __nv_bfloat16 g_awh[CC*3*CC],    g_awl[CC*3*CC];
__device__ __nv_bfloat16 g_pwh[CC*CC],      g_pwl[CC*CC];
__device__ __nv_bfloat16 g_audh[BB*AT*AD],  g_audl[BB*AT*AD];
__device__ __nv_bfloat16 g_wkwh[AD*AD],     g_wkwl[AD*AD];
__device__ __nv_bfloat16 g_wvwh[AD*AD],     g_wvwl[AD*AD];
__device__ __nv_bfloat16 g_pdnh[AD*DHID],   g_pdnl[AD*DHID];
__device__ __nv_bfloat16 g_puph[DHID*AD],   g_pupl[DHID*AD];
__device__ __nv_bfloat16 g_pqh[HS*HS],      g_pql[HS*HS];
__device__ __nv_bfloat16 g_qph[BB*NH*TT*HS],g_qpl[BB*NH*TT*HS];
__device__ __nv_bfloat16 g_q2h[BB*NH*TT*HS],g_q2l[BB*NH*TT*HS];
__device__ __nv_bfloat16 g_prefh[ALEN*CC],  g_prefl[ALEN*CC];
__device__ __nv_bfloat16 g_wknh[BB*AT*AD],  g_wknl[BB*AT*AD];
__device__ __nv_bfloat16 g_wvnh[BB*AT*AD],  g_wvnl[BB*AT*AD];
__device__ __nv_bfloat16 g_hidh[BB*AT*DHID],g_hidl[BB*AT*DHID];
__device__ __nv_bfloat16 g_ybth[BB*TT*CC],  g_ybtl[BB*TT*CC];
// attention K/V planes
__device__ __nv_bfloat16 g_kh[BB*NH*TT*HS], g_kl[BB*NH*TT*HS];
__device__ __nv_bfloat16 g_vh[BB*NH*TT*HS], g_vl[BB*NH*TT*HS];
__device__ __nv_bfloat16 g_akh[NH*ALEN*HS], g_akl[NH*ALEN*HS];
__device__ __nv_bfloat16 g_avh[NH*ALEN*HS], g_avl[NH*ALEN*HS];
__device__ __nv_bfloat16 g_pkh[BB*NH*AT*HS],g_pkl[BB*NH*AT*HS];
__device__ __nv_bfloat16 g_pvh[BB*NH*AT*HS],g_pvl[BB*NH*AT*HS];

// ================= helpers =================
__device__ __forceinline__ uint32_t smem_u32(const void* p) {
    uint32_t a;
    asm("{ .reg .u64 t; cvta.to.shared.u64 t, %1; cvt.u32.u64 %0, t; }" : "=r"(a) : "l"(p));
    return a;
}

#define LDSM_X4(r, addr) \
    asm volatile("ldmatrix.sync.aligned.m8n8.x4.shared.b16 {%0,%1,%2,%3}, [%4];" \
        : "=r"((r)[0]), "=r"((r)[1]), "=r"((r)[2]), "=r"((r)[3]) : "r"(addr))
#define LDSM_X4_T(r, addr) \
    asm volatile("ldmatrix.sync.aligned.m8n8.x4.trans.shared.b16 {%0,%1,%2,%3}, [%4];" \
        : "=r"((r)[0]), "=r"((r)[1]), "=r"((r)[2]), "=r"((r)[3]) : "r"(addr))
#define MMA_BF16(c, a, b) \
    asm volatile("mma.sync.aligned.m16n8k16.row.col.f32.bf16.bf16.f32 " \
        "{%0,%1,%2,%3}, {%4,%5,%6,%7}, {%8,%9}, {%0,%1,%2,%3};" \
        : "+f"((c)[0]), "+f"((c)[1]), "+f"((c)[2]), "+f"((c)[3]) \
        : "r"((a)[0]), "r"((a)[1]), "r"((a)[2]), "r"((a)[3]), "r"((b)[0]), "r"((b)[1]))

__device__ __forceinline__ void cp_async16(uint32_t dst, const void* src, bool pred) {
    int sz = pred ? 16 : 0;
    asm volatile("cp.async.cg.shared.global [%0], [%1], 16, %2;"
                 :: "r"(dst), "l"(src), "r"(sz) : "memory");
}
#define CP_COMMIT() asm volatile("cp.async.commit_group;" ::: "memory")
#define CP_WAIT1()  asm volatile("cp.async.wait_group 1;"  ::: "memory")
#define CP_WAIT0()  asm volatile("cp.async.wait_group 0;"  ::: "memory")

__device__ __forceinline__ uint32_t pack_bf2(float a, float b) {
    __nv_bfloat162 t = __floats2bfloat162_rn(a, b);
    return *(uint32_t*)&t;
}
__device__ __forceinline__ void trunc_split4(const float4 v, uint2& hi, uint2& lo) {
    uint32_t x = __float_as_uint(v.x), y = __float_as_uint(v.y);
    uint32_t z = __float_as_uint(v.z), w = __float_as_uint(v.w);
    hi.x = __byte_perm(x, y, 0x7632);
    hi.y = __byte_perm(z, w, 0x7632);
    float r0 = v.x - __uint_as_float(x & 0xffff0000u);
    float r1 = v.y - __uint_as_float(y & 0xffff0000u);
    float r2 = v.z - __uint_as_float(z & 0xffff0000u);
    float r3 = v.w - __uint_as_float(w & 0xffff0000u);
    lo.x = pack_bf2(r0, r1);
    lo.y = pack_bf2(r2, r3);
}
__device__ __forceinline__ void split2(float a, float b, uint32_t& hi, uint32_t& lo) {
    uint32_t ua = __float_as_uint(a), ub = __float_as_uint(b);
    hi = __byte_perm(ua, ub, 0x7632);
    float ra = a - __uint_as_float(ua & 0xffff0000u);
    float rb = b - __uint_as_float(ub & 0xffff0000u);
    lo = pack_bf2(ra, rb);
}

// ================= fp32 -> bf16 plane converter =================
__global__ void convert_kernel(const float* __restrict__ in,
                               __nv_bfloat16* __restrict__ h, __nv_bfloat16* __restrict__ l,
                               int n4)
{
    int half = (n4 + 1) >> 1;
    int i0 = blockIdx.x * blockDim.x + threadIdx.x;
    if (i0 >= half) return;
    int i1 = i0 + half;
    float4 v0 = ((const float4*)in)[i0];
    float4 v1 = (i1 < n4) ? ((const float4*)in)[i1] : make_float4(0,0,0,0);
    uint2 h0, l0, h1, l1;
    trunc_split4(v0, h0, l0);
    trunc_split4(v1, h1, l1);
    ((uint2*)h)[i0] = h0;
    ((uint2*)l)[i0] = l0;
    if (i1 < n4) {
        ((uint2*)h)[i1] = h1;
        ((uint2*)l)[i1] = l1;
    }
}

// ================= plane GEMM, 3 CTAs/SM =================
// mode: bit0 silu; bit1 write planes Ch/Cl; bit2 fused rope/qkv-split output
//       (M rows = (b,t); N cols in [0,3C): q | k | v; writes q/k/v planes).
#define NSTAGE 3
#define STAGE_BYTES 24576
#define GEMM_SMEM_BYTES (NSTAGE * STAGE_BYTES)

__global__ __launch_bounds__(128, 3) void gemm_planes_kernel(
    const __nv_bfloat16* __restrict__ Ah, const __nv_bfloat16* __restrict__ Al,
    const __nv_bfloat16* __restrict__ Bh, const __nv_bfloat16* __restrict__ Bl,
    float* __restrict__ C, __nv_bfloat16* __restrict__ Ch, __nv_bfloat16* __restrict__ Cl,
    int M, int N, int K, const float* __restrict__ bias, int mode,
    const float* __restrict__ cosp, const float* __restrict__ sinp,
    __nv_bfloat16* __restrict__ rqh, __nv_bfloat16* __restrict__ rql,
    __nv_bfloat16* __restrict__ rkh, __nv_bfloat16* __restrict__ rkl,
    __nv_bfloat16* __restrict__ rvh, __nv_bfloat16* __restrict__ rvl)
{
    extern __shared__ __align__(128) unsigned char smem[];
    const uint32_t sbase = smem_u32(smem);
    const int tid = threadIdx.x;
    const int lane = tid & 31, warp = tid >> 5;
    const int wm = warp & 1, wn = warp >> 1;
    const int m0 = blockIdx.x * 128, n0 = blockIdx.y * 64;
    const int nkt = (K + 31) / 32;

    auto issue = [&](int t) {
        if (t < nkt) {
            uint32_t sB = sbase + (uint32_t)(t % NSTAGE) * STAGE_BYTES;
            int kt = t;
#pragma unroll
            for (int u = 0; u < 4; u++) {
                int idx = u * 128 + tid;
                int row = idx >> 2, g = idx & 3;
                int gk = kt * 32 + g * 8;
                bool p = (m0 + row < M) && (gk < K);
                long off = (long)(m0 + row) * K + gk;
                uint32_t dst = sB + (uint32_t)row * 64u + (uint32_t)((g ^ ((row >> 1) & 3)) << 4);
                cp_async16(dst,         Ah + off, p);
                cp_async16(dst + 8192u, Al + off, p);
            }
#pragma unroll
            for (int u = 0; u < 2; u++) {
                int idx = u * 128 + tid;
                int row = idx >> 3, g = idx & 7;
                int gk = kt * 32 + row;
                int gn = n0 + g * 8;
                bool p = (gk < K) && (gn < N);
                long off = (long)gk * N + gn;
                uint32_t gs = (uint32_t)g ^ ((uint32_t)row & 7u);
                uint32_t dst = sB + 16384u + (uint32_t)row * 128u + (gs << 4);
                cp_async16(dst,         Bh + off, p);
                cp_async16(dst + 4096u, Bl + off, p);
            }
        }
        CP_COMMIT();
    };

    float acc[4][4][4];
#pragma unroll
    for (int i = 0; i < 4; i++)
#pragma unroll
        for (int j = 0; j < 4; j++)
#pragma unroll
            for (int e = 0; e < 4; e++) acc[i][j][e] = 0.f;

    issue(0); issue(1);

    for (int t = 0; t < nkt; t++) {
        CP_WAIT1();
        __syncthreads();
        issue(t + 2);
        uint32_t aB = sbase + (uint32_t)(t % NSTAGE) * STAGE_BYTES;
        uint32_t bB = aB + 16384u;
#pragma unroll
        for (int ks = 0; ks < 2; ks++) {
            uint32_t ah[4][4], al[4][4], bh4[2][4], bl4[2][4];
#pragma unroll
            for (int i = 0; i < 4; i++) {
                uint32_t row = (uint32_t)(wm * 64 + i * 16 + (lane & 15));
                uint32_t lg = (uint32_t)(ks * 2) + ((uint32_t)lane >> 4);
                uint32_t addr = aB + row * 64u + ((lg ^ ((row >> 1) & 3u)) << 4);
                LDSM_X4(ah[i], addr);
                LDSM_X4(al[i], addr + 8192u);
            }
#pragma unroll
            for (int j2 = 0; j2 < 2; j2++) {
                uint32_t row = (uint32_t)(ks * 16) + (((uint32_t)lane >> 3) & 1u) * 8u + ((uint32_t)lane & 7u);
                uint32_t g = (uint32_t)(wn * 4 + j2 * 2) + ((uint32_t)lane >> 4);
                uint32_t gs = g ^ (row & 7u);
                uint32_t addr = bB + row * 128u + (gs << 4);
                LDSM_X4_T(bh4[j2], addr);
                LDSM_X4_T(bl4[j2], addr + 4096u);
            }
#pragma unroll
            for (int i = 0; i < 4; i++)
#pragma unroll
                for (int j = 0; j < 4; j++) {
                    uint32_t* bh = &bh4[j >> 1][(j & 1) * 2];
                    uint32_t* bl = &bl4[j >> 1][(j & 1) * 2];
                    MMA_BF16(acc[i][j], ah[i], bh);
                    MMA_BF16(acc[i][j], ah[i], bl);
                    MMA_BF16(acc[i][j], al[i], bh);
                }
        }
    }

#pragma unroll
    for (int i = 0; i < 4; i++) {
#pragma unroll
        for (int j = 0; j < 4; j++) {
            int gc = n0 + wn * 32 + j * 8 + (lane & 3) * 2;
            float b0v = 0.f, b1v = 0.f;
            if (bias && gc + 1 < N) { b0v = bias[gc]; b1v = bias[gc + 1]; }
#pragma unroll
            for (int half = 0; half < 2; half++) {
                int gr = m0 + wm * 64 + i * 16 + (lane >> 2) + half * 8;
                if (gr >= M || gc + 1 >= N) continue;
                float v0 = acc[i][j][half * 2 + 0] + b0v;
                float v1 = acc[i][j][half * 2 + 1] + b1v;
                if (mode & 1) {
                    v0 = v0 / (1.f + __expf(-v0));
                    v1 = v1 / (1.f + __expf(-v1));
                }
                if (mode & 4) {
                    // fused rope + qkv split -> planes
                    int bb = gr >> 10, tt = gr & 1023;       // gr = b*TT + t
                    int region = gc >> 12;                   // /CC
                    int hh = (gc >> 7) & 31;                 // head
                    int d = gc & 127;                        // even
                    float o0 = v0, o1 = v1;
                    if (region < 2) {
                        float cth = cosp[tt * 64 + (d >> 1)];
                        float sth = sinp[tt * 64 + (d >> 1)];
                        o0 = v0 * cth - v1 * sth;
                        o1 = v1 * cth + v0 * sth;
                    }
                    long dst = (((long)(bb * NH + hh)) * TT + tt) * HS + d;
                    uint32_t hi, lo;
                    split2(o0, o1, hi, lo);
                    if (region == 0)      { *(uint32_t*)&rqh[dst] = hi; *(uint32_t*)&rql[dst] = lo; }
                    else if (region == 1) { *(uint32_t*)&rkh[dst] = hi; *(uint32_t*)&rkl[dst] = lo; }
                    else                  { *(uint32_t*)&rvh[dst] = hi; *(uint32_t*)&rvl[dst] = lo; }
                } else if (mode & 2) {
                    long off = (long)gr * N + gc;
                    uint32_t hi, lo;
                    split2(v0, v1, hi, lo);
                    *(uint32_t*)&Ch[off] = hi;
                    *(uint32_t*)&Cl[off] = lo;
                } else {
                    long off = (long)gr * N + gc;
                    *(float2*)&C[off] = make_float2(v0, v1);
                }
            }
        }
    }
}

// ====== tensor-core flash attention: Q planes, bulk cp.async K/V ======
// outmode: 0 = write fp32 Out; 1 = accumulate into fp32 Out;
//          2 = read fp32 Out, add, write transposed [B,T,C] bf16 planes Oh/Ol.
#define ATTN_SMEM_BYTES 65536

__global__ __launch_bounds__(128, 1) void attn_mma_kernel(
    const __nv_bfloat16* __restrict__ Qh, const __nv_bfloat16* __restrict__ Ql,
    const __nv_bfloat16* __restrict__ Kh, const __nv_bfloat16* __restrict__ Kl,
    const __nv_bfloat16* __restrict__ Vh, const __nv_bfloat16* __restrict__ Vl,
    float* __restrict__ Out, __nv_bfloat16* __restrict__ Oh, __nv_bfloat16* __restrict__ Ol,
    int H, int Tq, int Tk,
    long kvbs, long kvhs, int causal, const float* __restrict__ gatep, int outmode)
{
    extern __shared__ __align__(128) unsigned char smem[];
    const uint32_t sb = smem_u32(smem);
    const int tid = threadIdx.x, lane = tid & 31, warp = tid >> 5;
    const int q0 = blockIdx.x * 64, h = blockIdx.y, b = blockIdx.z;
    const long qbase = ((long)(b * H + h)) * Tq * 128;
    const long kbase = (long)b * kvbs + (long)h * kvhs;
    const int qw = q0 + warp * 16;
    const int r0 = lane >> 2;
    const int c2 = (lane & 3) * 2;
    const uint32_t ln7 = lane & 7u;

    uint32_t qh[8][4], ql[8][4];
    {
        long ob0 = qbase + (long)(qw + r0) * 128;
        long ob1 = ob0 + 8 * 128;
#pragma unroll
        for (int kc = 0; kc < 8; kc++) {
            int cc0 = kc * 16 + c2, cc1 = kc * 16 + c2 + 8;
            qh[kc][0] = *(const uint32_t*)&Qh[ob0 + cc0];
            qh[kc][1] = *(const uint32_t*)&Qh[ob1 + cc0];
            qh[kc][2] = *(const uint32_t*)&Qh[ob0 + cc1];
            qh[kc][3] = *(const uint32_t*)&Qh[ob1 + cc1];
            ql[kc][0] = *(const uint32_t*)&Ql[ob0 + cc0];
            ql[kc][1] = *(const uint32_t*)&Ql[ob1 + cc0];
            ql[kc][2] = *(const uint32_t*)&Ql[ob0 + cc1];
            ql[kc][3] = *(const uint32_t*)&Ql[ob1 + cc1];
        }
    }

    float o[16][4];
#pragma unroll
    for (int n = 0; n < 16; n++)
#pragma unroll
        for (int e = 0; e < 4; e++) o[n][e] = 0.f;
    float m0v = -1e30f, m1v = -1e30f, l0v = 0.f, l1v = 0.f;

    const int kend = causal ? min(Tk, q0 + 64) : Tk;

    for (int kt = 0; kt < kend; kt += 64) {
        __syncthreads();
#pragma unroll
        for (int u = 0; u < 8; u++) {
            int idx = u * 128 + tid;
            int r = idx >> 4, g = idx & 15;
            bool p = (kt + r < Tk);
            long off = kbase + (long)(kt + r) * 128 + g * 8;
            uint32_t gs = ((uint32_t)g & 8u) | (((uint32_t)g & 7u) ^ ((uint32_t)r & 7u));
            uint32_t dst = sb + (uint32_t)r * 256u + (gs << 4);
            cp_async16(dst,          Kh + off, p);
            cp_async16(dst + 16384u, Kl + off, p);
            cp_async16(dst + 32768u, Vh + off, p);
            cp_async16(dst + 49152u, Vl + off, p);
        }
        CP_COMMIT();
        CP_WAIT0();
        __syncthreads();

        float s[8][4];
#pragma unroll
        for (int n = 0; n < 8; n++)
#pragma unroll
            for (int e = 0; e < 4; e++) s[n][e] = 0.f;

#pragma unroll
        for (int kc2 = 0; kc2 < 4; kc2++) {
#pragma unroll
            for (int nc = 0; nc < 8; nc++) {
                uint32_t row = (uint32_t)(nc * 8) + ln7;
                uint32_t g = (uint32_t)(kc2 * 4) + (uint32_t)(lane >> 3);
                uint32_t gs = (g & 8u) | ((g & 7u) ^ (row & 7u));
                uint32_t addr = sb + row * 256u + gs * 16u;
                uint32_t kh4[4], kl4[4];
                LDSM_X4(kh4, addr);
                LDSM_X4(kl4, addr + 16384u);
                MMA_BF16(s[nc], qh[2 * kc2],     &kh4[0]);
                MMA_BF16(s[nc], ql[2 * kc2],     &kh4[0]);
                MMA_BF16(s[nc], qh[2 * kc2],     &kl4[0]);
                MMA_BF16(s[nc], qh[2 * kc2 + 1], &kh4[2]);
                MMA_BF16(s[nc], ql[2 * kc2 + 1], &kh4[2]);
                MMA_BF16(s[nc], qh[2 * kc2 + 1], &kl4[2]);
            }
        }

#pragma unroll
        for (int nc = 0; nc < 8; nc++) {
#pragma unroll
            for (int e = 0; e < 4; e++) s[nc][e] *= ATT_SCALE;
        }

        if ((kt + 64 > Tk) || (causal && (kt + 63 >= qw))) {
#pragma unroll
            for (int nc = 0; nc < 8; nc++) {
#pragma unroll
                for (int e = 0; e < 4; e++) {
                    int kk = kt + nc * 8 + c2 + (e & 1);
                    int qr = qw + r0 + ((e >= 2) ? 8 : 0);
                    if (kk >= Tk || (causal && kk > qr)) s[nc][e] = -1e30f;
                }
            }
        }

        float mt0 = -1e30f, mt1 = -1e30f;
#pragma unroll
        for (int nc = 0; nc < 8; nc++) {
            mt0 = fmaxf(mt0, fmaxf(s[nc][0], s[nc][1]));
            mt1 = fmaxf(mt1, fmaxf(s[nc][2], s[nc][3]));
        }
        mt0 = fmaxf(mt0, __shfl_xor_sync(0xffffffffu, mt0, 1));
        mt0 = fmaxf(mt0, __shfl_xor_sync(0xffffffffu, mt0, 2));
        mt1 = fmaxf(mt1, __shfl_xor_sync(0xffffffffu, mt1, 1));
        mt1 = fmaxf(mt1, __shfl_xor_sync(0xffffffffu, mt1, 2));
        float mn0 = fmaxf(m0v, mt0), mn1 = fmaxf(m1v, mt1);
        float corr0 = __expf(m0v - mn0), corr1 = __expf(m1v - mn1);
        m0v = mn0; m1v = mn1;

        uint32_t ph[4][4], pl[4][4];
        float ps0 = 0.f, ps1 = 0.f;
#pragma unroll
        for (int nc = 0; nc < 8; nc++) {
            float p0 = __expf(s[nc][0] - mn0);
            float p1 = __expf(s[nc][1] - mn0);
            float p2 = __expf(s[nc][2] - mn1);
            float p3 = __expf(s[nc][3] - mn1);
            ps0 += p0 + p1; ps1 += p2 + p3;
            uint32_t h01, l01, h23, l23;
            split2(p0, p1, h01, l01);
            split2(p2, p3, h23, l23);
            int kc = nc >> 1;
            if ((nc & 1) == 0) { ph[kc][0] = h01; ph[kc][1] = h23; pl[kc][0] = l01; pl[kc][1] = l23; }
            else               { ph[kc][2] = h01; ph[kc][3] = h23; pl[kc][2] = l01; pl[kc][3] = l23; }
        }
        ps0 += __shfl_xor_sync(0xffffffffu, ps0, 1);
        ps0 += __shfl_xor_sync(0xffffffffu, ps0, 2);
        ps1 += __shfl_xor_sync(0xffffffffu, ps1, 1);
        ps1 += __shfl_xor_sync(0xffffffffu, ps1, 2);
        l0v = l0v * corr0 + ps0;
        l1v = l1v * corr1 + ps1;

#pragma unroll
        for (int n = 0; n < 16; n++) {
            o[n][0] *= corr0; o[n][1] *= corr0;
            o[n][2] *= corr1; o[n][3] *= corr1;
        }

#pragma unroll
        for (int kc = 0; kc < 4; kc++) {
            uint32_t row = (uint32_t)(kc * 16) + ((uint32_t)((lane >> 3) & 1)) * 8u + ln7;
#pragma unroll
            for (int dp = 0; dp < 8; dp++) {
                uint32_t g = (uint32_t)(dp * 2) + (uint32_t)(lane >> 4);
                uint32_t gs = (g & 8u) | ((g & 7u) ^ (row & 7u));
                uint32_t addr = sb + 32768u + row * 256u + gs * 16u;
                uint32_t vh4[4], vl4[4];
                LDSM_X4_T(vh4, addr);
                LDSM_X4_T(vl4, addr + 16384u);
                MMA_BF16(o[2 * dp],     ph[kc], &vh4[0]);
                MMA_BF16(o[2 * dp],     pl[kc], &vh4[0]);
                MMA_BF16(o[2 * dp],     ph[kc], &vl4[0]);
                MMA_BF16(o[2 * dp + 1], ph[kc], &vh4[2]);
                MMA_BF16(o[2 * dp + 1], pl[kc], &vh4[2]);
                MMA_BF16(o[2 * dp + 1], ph[kc], &vl4[2]);
            }
        }
    }

    float gate = gatep ? *gatep : 1.f;
    float sc0 = gate / l0v, sc1 = gate / l1v;
#pragma unroll
    for (int n = 0; n < 16; n++) {
        int gc = n * 8 + c2;
        long off0 = qbase + (long)(qw + r0) * 128 + gc;
        long off1 = off0 + 8 * 128;
        float2 v0 = make_float2(o[n][0] * sc0, o[n][1] * sc0);
        float2 v1 = make_float2(o[n][2] * sc1, o[n][3] * sc1);
        if (outmode >= 1) {
            float2 p0 = *(const float2*)&Out[off0];
            float2 p1 = *(const float2*)&Out[off1];
            v0.x += p0.x; v0.y += p0.y;
            v1.x += p1.x; v1.y += p1.y;
        }
        if (outmode == 2) {
            long offT0 = ((long)b * Tq + qw + r0) * (long)(H * 128) + (long)h * 128 + gc;
            long offT1 = offT0 + (long)8 * (H * 128);
            uint32_t hi, lo;
            split2(v0.x, v0.y, hi, lo);
            *(uint32_t*)&Oh[offT0] = hi;
            *(uint32_t*)&Ol[offT0] = lo;
            split2(v1.x, v1.y, hi, lo);
            *(uint32_t*)&Oh[offT1] = hi;
            *(uint32_t*)&Ol[offT1] = lo;
        } else {
            *(float2*)&Out[off0] = v0;
            *(float2*)&Out[off1] = v1;
        }
    }
}

// ================= rmsnorm per row -> bf16 planes =================
__global__ void rmsnorm_planes_kernel(const float* __restrict__ in, const float* __restrict__ w,
                                      __nv_bfloat16* __restrict__ oh, __nv_bfloat16* __restrict__ ol,
                                      int N)
{
    int row = blockIdx.x;
    const float* x = in + (long)row * N;
    float ss = 0.f;
    for (int c = threadIdx.x; c < N; c += 256) { float v = x[c]; ss = fmaf(v, v, ss); }
    __shared__ float sh[32];
    int lane = threadIdx.x & 31, wid = threadIdx.x >> 5;
#pragma unroll
    for (int o = 16; o; o >>= 1) ss += __shfl_xor_sync(0xffffffffu, ss, o);
    if (lane == 0) sh[wid] = ss;
    __syncthreads();
    float tot = (threadIdx.x < 8) ? sh[threadIdx.x] : 0.f;
    if (wid == 0) {
#pragma unroll
        for (int o = 16; o; o >>= 1) tot += __shfl_xor_sync(0xffffffffu, tot, o);
    }
    __shared__ float ssc;
    if (threadIdx.x == 0) ssc = rsqrtf(tot / (float)N + 1e-5f);
    __syncthreads();
    float sc = ssc;
    for (int c = threadIdx.x * 2; c < N; c += 512) {
        float v0 = x[c] * sc * w[c];
        float v1 = x[c + 1] * sc * w[c + 1];
        uint32_t hi, lo;
        split2(v0, v1, hi, lo);
        *(uint32_t*)&oh[(long)row * N + c] = hi;
        *(uint32_t*)&ol[(long)row * N + c] = lo;
    }
}

// ================= adapter split -> planes =================
__global__ void adapter_split_kernel(const float* __restrict__ aqkv,
                                     __nv_bfloat16* __restrict__ akh, __nv_bfloat16* __restrict__ akl,
                                     __nv_bfloat16* __restrict__ avh, __nv_bfloat16* __restrict__ avl)
{
    int idx2 = blockIdx.x * blockDim.x + threadIdx.x;
    if (idx2 >= NH * ALEN * HS / 2) return;
    int idx = idx2 * 2;
    int d = idx & 127;
    int a = (idx >> 7) % ALEN;
    int h = idx / (ALEN * HS);
    long src = (long)a * (3 * CC) + h * HS + d;
    uint32_t hi, lo;
    split2(aqkv[src + CC], aqkv[src + CC + 1], hi, lo);
    *(uint32_t*)&akh[idx] = hi;
    *(uint32_t*)&akl[idx] = lo;
    split2(aqkv[src + 2*CC], aqkv[src + 2*CC + 1], hi, lo);
    *(uint32_t*)&avh[idx] = hi;
    *(uint32_t*)&avl[idx] = lo;
}

// ================= assemble pk/pv -> planes =================
__global__ void fill_pkv_kernel(const float* __restrict__ wflat, const float* __restrict__ pad,
                                __nv_bfloat16* __restrict__ ph, __nv_bfloat16* __restrict__ pl)
{
    int idx2 = blockIdx.x * blockDim.x + threadIdx.x;
    if (idx2 >= BB * NH * AT * HS / 2) return;
    int idx = idx2 * 2;
    int d = idx & 127;
    int t = (idx >> 7) % AT;
    int h = (idx / (HS * AT)) & 31;
    int b = idx / (HS * AT * NH);
    float v0, v1;
    if (h < NWH && d < WHD) {
        long src = (long)b * (AT * AD) + h * (AT * WHD) + t * WHD + d;
        v0 = wflat[src]; v1 = wflat[src + 1];
    } else {
        long src = ((long)b * AT + t) * HS + d;
        v0 = pad[src]; v1 = pad[src + 1];
    }
    uint32_t hi, lo;
    split2(v0, v1, hi, lo);
    *(uint32_t*)&ph[idx] = hi;
    *(uint32_t*)&pl[idx] = lo;
}

// ================= head mix -> q2 planes =================
__global__ __launch_bounds__(256) void headmix_kernel(const float* __restrict__ q2a,
                                                      const float* __restrict__ w,
                                                      __nv_bfloat16* __restrict__ q2h,
                                                      __nv_bfloat16* __restrict__ q2l)
{
    int bt = blockIdx.x;
    int b = bt >> 10, t = bt & 1023;
    __shared__ float sm[NH * HS];
    __shared__ float ws[NH * NH];
    for (int i = threadIdx.x; i < NH * HS; i += 256) {
        int h = i >> 7, d = i & 127;
        sm[i] = q2a[(((long)(b * NH + h)) * TT + t) * HS + d];
    }
    for (int i = threadIdx.x; i < NH * NH; i += 256) ws[i] = w[i];
    __syncthreads();
    for (int i2 = threadIdx.x; i2 < NH * HS / 2; i2 += 256) {
        int i = i2 * 2;
        int g = i >> 7, d = i & 127;
        float acc0 = 0.f, acc1 = 0.f;
#pragma unroll
        for (int h = 0; h < NH; h++) {
            float wv = ws[h * NH + g];
            acc0 = fmaf(sm[h * HS + d],     wv, acc0);
            acc1 = fmaf(sm[h * HS + d + 1], wv, acc1);
        }
        long dst = (((long)(b * NH + g)) * TT + t) * HS + d;
        uint32_t hi, lo;
        split2(acc0, acc1, hi, lo);
        *(uint32_t*)&q2h[dst] = hi;
        *(uint32_t*)&q2l[dst] = lo;
    }
}

// ================= host launcher =================
static float* symp(const void* symbol)
{
    void* p = nullptr;
    cudaGetSymbolAddress(&p, symbol);
    return (float*)p;
}
static __nv_bfloat16* symb(const void* symbol)
{
    void* p = nullptr;
    cudaGetSymbolAddress(&p, symbol);
    return (__nv_bfloat16*)p;
}

static inline void gemm_pl(const __nv_bfloat16* Ah, const __nv_bfloat16* Al,
                           const __nv_bfloat16* Bh, const __nv_bfloat16* Bl,
                           float* C, __nv_bfloat16* Ch, __nv_bfloat16* Cl,
                           int M, int N, int K, const float* bias, int mode,
                           const float* cosp = nullptr, const float* sinp = nullptr,
                           __nv_bfloat16* rqh = nullptr, __nv_bfloat16* rql = nullptr,
                           __nv_bfloat16* rkh = nullptr, __nv_bfloat16* rkl = nullptr,
                           __nv_bfloat16* rvh = nullptr, __nv_bfloat16* rvl = nullptr)
{
    dim3 grid((M + 127) / 128, (N + 63) / 64);
    gemm_planes_kernel<<<grid, 128, GEMM_SMEM_BYTES>>>(Ah, Al, Bh, Bl, C, Ch, Cl,
        M, N, K, bias, mode, cosp, sinp, rqh, rql, rkh, rkl, rvh, rvl);
}

static inline void convert(const float* in, __nv_bfloat16* h, __nv_bfloat16* l, long n)
{
    int n4 = (int)(n / 4);
    int half = (n4 + 1) >> 1;
    convert_kernel<<<(half + 255) / 256, 256>>>(in, h, l, n4);
}

extern "C" void kernel_launch(void* const* d_in, const int* in_sizes, int n_in,
                              void* d_out, int out_size)
{
    (void)in_sizes; (void)n_in; (void)out_size;
    const float* x        = (const float*)d_in[0];
    const float* audio    = (const float*)d_in[1];
    const float* rope_cos = (const float*)d_in[2];
    const float* rope_sin = (const float*)d_in[3];
    const float* pad_k    = (const float*)d_in[6];
    const float* pad_v    = (const float*)d_in[7];
    const float* c_attn_w = (const float*)d_in[8];
    const float* c_proj_w = (const float*)d_in[9];
    const float* adapter  = (const float*)d_in[10];
    const float* gating   = (const float*)d_in[11];
    const float* rms_gate = (const float*)d_in[12];
    const float* rms_key  = (const float*)d_in[13];
    const float* rms_val  = (const float*)d_in[14];
    const float* proj_dn  = (const float*)d_in[15];
    const float* proj_up  = (const float*)d_in[16];
    const float* pq128    = (const float*)d_in[17];
    const float* pq32     = (const float*)d_in[18];
    const float* pgating  = (const float*)d_in[19];
    const float* wkw      = (const float*)d_in[20];
    const float* wvw      = (const float*)d_in[21];
    const float* wvb      = (const float*)d_in[22];
    float* out = (float*)d_out;

    float *y = symp(g_y);
    float *aqkv = symp(g_aqkv);
    float *wkn = symp(g_wkn), *wvn = symp(g_wvn), *wk = symp(g_wk), *wv = symp(g_wv);
    float *q2a = symp(g_q2a);

    __nv_bfloat16 *xh = symb(g_xh), *xl = symb(g_xl);
    __nv_bfloat16 *awh = symb(g_awh), *awl = symb(g_awl);
    __nv_bfloat16 *pwh = symb(g_pwh), *pwl = symb(g_pwl);
    __nv_bfloat16 *audh = symb(g_audh), *audl = symb(g_audl);
    __nv_bfloat16 *wkwh = symb(g_wkwh), *wkwl = symb(g_wkwl);
    __nv_bfloat16 *wvwh = symb(g_wvwh), *wvwl = symb(g_wvwl);
    __nv_bfloat16 *pdnh = symb(g_pdnh), *pdnl = symb(g_pdnl);
    __nv_bfloat16 *puph = symb(g_puph), *pupl = symb(g_pupl);
    __nv_bfloat16 *pqh = symb(g_pqh), *pql = symb(g_pql);
    __nv_bfloat16 *qph = symb(g_qph), *qpl = symb(g_qpl);
    __nv_bfloat16 *q2h = symb(g_q2h), *q2l = symb(g_q2l);
    __nv_bfloat16 *prefh = symb(g_prefh), *prefl = symb(g_prefl);
    __nv_bfloat16 *wknh = symb(g_wknh), *wknl = symb(g_wknl);
    __nv_bfloat16 *wvnh = symb(g_wvnh), *wvnl = symb(g_wvnl);
    __nv_bfloat16 *hidh = symb(g_hidh), *hidl = symb(g_hidl);
    __nv_bfloat16 *ybth = symb(g_ybth), *ybtl = symb(g_ybtl);
    __nv_bfloat16 *kh = symb(g_kh), *kl = symb(g_kl), *vh = symb(g_vh), *vl = symb(g_vl);
    __nv_bfloat16 *akh = symb(g_akh), *akl = symb(g_akl), *avh = symb(g_avh), *avl = symb(g_avl);
    __nv_bfloat16 *pkh = symb(g_pkh), *pkl = symb(g_pkl), *pvh = symb(g_pvh), *pvl = symb(g_pvl);

    cudaFuncSetAttribute(gemm_planes_kernel, cudaFuncAttributeMaxDynamicSharedMemorySize,
                         GEMM_SMEM_BYTES);
    cudaFuncSetAttribute(attn_mma_kernel, cudaFuncAttributeMaxDynamicSharedMemorySize,
                         ATTN_SMEM_BYTES);

    const int M = BB * TT;            // 2048
    const int MA = BB * AT;           // 3000

    // 0) operand conversions
    convert(x, xh, xl, (long)BB*TT*CC);
    convert(c_attn_w, awh, awl, (long)CC*3*CC);
    convert(c_proj_w, pwh, pwl, (long)CC*CC);
    convert(audio, audh, audl, (long)BB*AT*AD);
    convert(wkw, wkwh, wkwl, (long)AD*AD);
    convert(wvw, wvwh, wvwl, (long)AD*AD);
    convert(proj_dn, pdnh, pdnl, (long)AD*DHID);
    convert(proj_up, puph, pupl, (long)DHID*AD);
    convert(pq128, pqh, pql, (long)HS*HS);

    // 1) qkv GEMM with fused rope + split -> q/k/v planes (no fp32 qkv buffer)
    gemm_pl(xh, xl, awh, awl, nullptr, nullptr, nullptr, M, 3*CC, CC, nullptr, 4,
            rope_cos, rope_sin, qph, qpl, kh, kl, vh, vl);

    // 3) causal self-attention -> y
    attn_mma_kernel<<<dim3(TT/64, NH, BB), 128, ATTN_SMEM_BYTES>>>(
        qph, qpl, kh, kl, vh, vl, y, nullptr, nullptr,
        NH, TT, TT, (long)NH*TT*HS, (long)TT*HS, 1, nullptr, 0);

    // 4) adapter branch
    rmsnorm_planes_kernel<<<ALEN, 256>>>(adapter, rms_gate, prefh, prefl, CC);
    gemm_pl(prefh, prefl, awh, awl, aqkv, nullptr, nullptr, ALEN, 3*CC, CC, nullptr, 0);
    adapter_split_kernel<<<(NH*ALEN*HS/2 + 255) / 256, 256>>>(aqkv, akh, akl, avh, avl);
    attn_mma_kernel<<<dim3(TT/64, NH, BB), 128, ATTN_SMEM_BYTES>>>(
        qph, qpl, akh, akl, avh, avl, y, nullptr, nullptr,
        NH, TT, ALEN, 0L, (long)ALEN*HS, 0, gating, 1);

    // 5) whisper key path
    gemm_pl(audh, audl, wkwh, wkwl, wkn, nullptr, nullptr, MA, AD, AD, nullptr, 0);
    rmsnorm_planes_kernel<<<MA, 256>>>(wkn, rms_key, wknh, wknl, AD);
    gemm_pl(wknh, wknl, pdnh, pdnl, nullptr, hidh, hidl, MA, DHID, AD, nullptr, 3);
    gemm_pl(hidh, hidl, puph, pupl, wk, nullptr, nullptr, MA, AD, DHID, nullptr, 0);

    // 6) whisper value path
    gemm_pl(audh, audl, wvwh, wvwl, wvn, nullptr, nullptr, MA, AD, AD, wvb, 0);
    rmsnorm_planes_kernel<<<MA, 256>>>(wvn, rms_val, wvnh, wvnl, AD);
    gemm_pl(wvnh, wvnl, pdnh, pdnl, nullptr, hidh, hidl, MA, DHID, AD, nullptr, 3);
    gemm_pl(hidh, hidl, puph, pupl, wv, nullptr, nullptr, MA, AD, DHID, nullptr, 0);

    // 7) assemble pk/pv planes
    {
        int tot2 = BB * NH * AT * HS / 2;
        fill_pkv_kernel<<<(tot2 + 255) / 256, 256>>>(wk, pad_k, pkh, pkl);
        fill_pkv_kernel<<<(tot2 + 255) / 256, 256>>>(wv, pad_v, pvh, pvl);
    }

    // 8) q2 = (q @ proj_q128) head-mixed by proj_q32 -> planes
    gemm_pl(qph, qpl, pqh, pql, q2a, nullptr, nullptr, BB*NH*TT, HS, HS, nullptr, 0);
    headmix_kernel<<<BB * TT, 256>>>(q2a, pq32, q2h, q2l);

    // 9) whisper cross-attention -> fused accumulate + transpose -> ybt planes
    attn_mma_kernel<<<dim3(TT/64, NH, BB), 128, ATTN_SMEM_BYTES>>>(
        q2h, q2l, pkh, pkl, pvh, pvl, y, ybth, ybtl,
        NH, TT, AT, (long)NH*AT*HS, (long)AT*HS, 0, pgating, 2);

    // 10) output projection
    gemm_pl(ybth, ybtl, pwh, pwl, out, nullptr, nullptr, M, CC, CC, nullptr, 0);
}

// round 14
// speedup vs baseline: 1.0156x; 1.0156x over previous
#include <cuda_runtime.h>
#include <cuda_bf16.h>
#include <math.h>
#include <stdint.h>

// ---------------- problem constants ----------------
#define BB 2
#define TT 1024
#define CC 4096
#define NH 32
#define HS 128
#define ALEN 10
#define AT 1500
#define AD 1280
#define NWH 20
#define WHD 64
#define DHID 80           // AD/16
#define ATT_SCALE 0.08838834764831845f   // 1/sqrt(128)

// ---------------- fp32 scratch ----------------
__device__ float g_qkv [BB*TT*3*CC];
__device__ float g_y   [BB*NH*TT*HS];
__device__ float g_aqkv[ALEN*3*CC];
__device__ float g_wkn [BB*AT*AD];
__device__ float g_wvn [BB*AT*AD];
__device__ float g_wk  [BB*AT*AD];
__device__ float g_wv  [BB*AT*AD];
__device__ float g_q2a [BB*NH*TT*HS];

// ---------------- bf16 hi/lo plane scratch ----------------
__device__ __nv_bfloat16 g_xh[BB*TT*CC],    g_xl[BB*TT*CC];
__device__ __nv_bfloat16 g_awh[CC*3*CC],    g_awl[CC*3*CC];
__device__ __nv_bfloat16 g_pwh[CC*CC],      g_pwl[CC*CC];
__device__ __nv_bfloat16 g_audh[BB*AT*AD],  g_audl[BB*AT*AD];
__device__ __nv_bfloat16 g_wkwh[AD*AD],     g_wkwl[AD*AD];
__device__ __nv_bfloat16 g_wvwh[AD*AD],     g_wvwl[AD*AD];
__device__ __nv_bfloat16 g_pdnh[AD*DHID],   g_pdnl[AD*DHID];
__device__ __nv_bfloat16 g_puph[DHID*AD],   g_pupl[DHID*AD];
__device__ __nv_bfloat16 g_pqh[HS*HS],      g_pql[HS*HS];
__device__ __nv_bfloat16 g_qph[BB*NH*TT*HS],g_qpl[BB*NH*TT*HS];
__device__ __nv_bfloat16 g_q2h[BB*NH*TT*HS],g_q2l[BB*NH*TT*HS];
__device__ __nv_bfloat16 g_prefh[ALEN*CC],  g_prefl[ALEN*CC];
__device__ __nv_bfloat16 g_wknh[BB*AT*AD],  g_wknl[BB*AT*AD];
__device__ __nv_bfloat16 g_wvnh[BB*AT*AD],  g_wvnl[BB*AT*AD];
__device__ __nv_bfloat16 g_hidh[BB*AT*DHID],g_hidl[BB*AT*DHID];
__device__ __nv_bfloat16 g_ybth[BB*TT*CC],  g_ybtl[BB*TT*CC];
// attention K/V planes
__device__ __nv_bfloat16 g_kh[BB*NH*TT*HS], g_kl[BB*NH*TT*HS];
__device__ __nv_bfloat16 g_vh[BB*NH*TT*HS], g_vl[BB*NH*TT*HS];
__device__ __nv_bfloat16 g_akh[NH*ALEN*HS], g_akl[NH*ALEN*HS];
__device__ __nv_bfloat16 g_avh[NH*ALEN*HS], g_avl[NH*ALEN*HS];
__device__ __nv_bfloat16 g_pkh[BB*NH*AT*HS],g_pkl[BB*NH*AT*HS];
__device__ __nv_bfloat16 g_pvh[BB*NH*AT*HS],g_pvl[BB*NH*AT*HS];

// ================= helpers =================
__device__ __forceinline__ uint32_t smem_u32(const void* p) {
    uint32_t a;
    asm("{ .reg .u64 t; cvta.to.shared.u64 t, %1; cvt.u32.u64 %0, t; }" : "=r"(a) : "l"(p));
    return a;
}

#define LDSM_X4(r, addr) \
    asm volatile("ldmatrix.sync.aligned.m8n8.x4.shared.b16 {%0,%1,%2,%3}, [%4];" \
        : "=r"((r)[0]), "=r"((r)[1]), "=r"((r)[2]), "=r"((r)[3]) : "r"(addr))
#define LDSM_X4_T(r, addr) \
    asm volatile("ldmatrix.sync.aligned.m8n8.x4.trans.shared.b16 {%0,%1,%2,%3}, [%4];" \
        : "=r"((r)[0]), "=r"((r)[1]), "=r"((r)[2]), "=r"((r)[3]) : "r"(addr))
#define MMA_BF16(c, a, b) \
    asm volatile("mma.sync.aligned.m16n8k16.row.col.f32.bf16.bf16.f32 " \
        "{%0,%1,%2,%3}, {%4,%5,%6,%7}, {%8,%9}, {%0,%1,%2,%3};" \
        : "+f"((c)[0]), "+f"((c)[1]), "+f"((c)[2]), "+f"((c)[3]) \
        : "r"((a)[0]), "r"((a)[1]), "r"((a)[2]), "r"((a)[3]), "r"((b)[0]), "r"((b)[1]))

__device__ __forceinline__ void cp_async16(uint32_t dst, const void* src, bool pred) {
    int sz = pred ? 16 : 0;
    asm volatile("cp.async.cg.shared.global [%0], [%1], 16, %2;"
                 :: "r"(dst), "l"(src), "r"(sz) : "memory");
}
#define CP_COMMIT() asm volatile("cp.async.commit_group;" ::: "memory")
#define CP_WAIT1()  asm volatile("cp.async.wait_group 1;"  ::: "memory")
#define CP_WAIT0()  asm volatile("cp.async.wait_group 0;"  ::: "memory")

__device__ __forceinline__ uint32_t pack_bf2(float a, float b) {
    __nv_bfloat162 t = __floats2bfloat162_rn(a, b);
    return *(uint32_t*)&t;
}
__device__ __forceinline__ void trunc_split4(const float4 v, uint2& hi, uint2& lo) {
    uint32_t x = __float_as_uint(v.x), y = __float_as_uint(v.y);
    uint32_t z = __float_as_uint(v.z), w = __float_as_uint(v.w);
    hi.x = __byte_perm(x, y, 0x7632);
    hi.y = __byte_perm(z, w, 0x7632);
    float r0 = v.x - __uint_as_float(x & 0xffff0000u);
    float r1 = v.y - __uint_as_float(y & 0xffff0000u);
    float r2 = v.z - __uint_as_float(z & 0xffff0000u);
    float r3 = v.w - __uint_as_float(w & 0xffff0000u);
    lo.x = pack_bf2(r0, r1);
    lo.y = pack_bf2(r2, r3);
}
__device__ __forceinline__ void split2(float a, float b, uint32_t& hi, uint32_t& lo) {
    uint32_t ua = __float_as_uint(a), ub = __float_as_uint(b);
    hi = __byte_perm(ua, ub, 0x7632);
    float ra = a - __uint_as_float(ua & 0xffff0000u);
    float rb = b - __uint_as_float(ub & 0xffff0000u);
    lo = pack_bf2(ra, rb);
}

// ======== fp32 -> bf16 plane converter, 8 floats/thread, 16B stores ========
__global__ void convert_kernel(const float* __restrict__ in,
                               __nv_bfloat16* __restrict__ h, __nv_bfloat16* __restrict__ l,
                               int n8)
{
    int i = blockIdx.x * blockDim.x + threadIdx.x;
    if (i >= n8) return;
    float4 a = ((const float4*)in)[i * 2];
    float4 b = ((const float4*)in)[i * 2 + 1];
    uint2 h0, l0, h1, l1;
    trunc_split4(a, h0, l0);
    trunc_split4(b, h1, l1);
    uint4 H = make_uint4(h0.x, h0.y, h1.x, h1.y);
    uint4 L = make_uint4(l0.x, l0.y, l1.x, l1.y);
    ((uint4*)h)[i] = H;
    ((uint4*)l)[i] = L;
}

// ================= plane GEMM, 3 CTAs/SM (R8/R11 winner) =================
// mode: bit0 silu; bit1 write bf16 planes (Ch/Cl) instead of fp32 C.
#define NSTAGE 3
#define STAGE_BYTES 24576
#define GEMM_SMEM_BYTES (NSTAGE * STAGE_BYTES)

__global__ __launch_bounds__(128, 3) void gemm_planes_kernel(
    const __nv_bfloat16* __restrict__ Ah, const __nv_bfloat16* __restrict__ Al,
    const __nv_bfloat16* __restrict__ Bh, const __nv_bfloat16* __restrict__ Bl,
    float* __restrict__ C, __nv_bfloat16* __restrict__ Ch, __nv_bfloat16* __restrict__ Cl,
    int M, int N, int K, const float* __restrict__ bias, int mode)
{
    extern __shared__ __align__(128) unsigned char smem[];
    const uint32_t sbase = smem_u32(smem);
    const int tid = threadIdx.x;
    const int lane = tid & 31, warp = tid >> 5;
    const int wm = warp & 1, wn = warp >> 1;
    const int m0 = blockIdx.x * 128, n0 = blockIdx.y * 64;
    const int nkt = (K + 31) / 32;

    auto issue = [&](int t) {
        if (t < nkt) {
            uint32_t sB = sbase + (uint32_t)(t % NSTAGE) * STAGE_BYTES;
            int kt = t;
#pragma unroll
            for (int u = 0; u < 4; u++) {
                int idx = u * 128 + tid;
                int row = idx >> 2, g = idx & 3;
                int gk = kt * 32 + g * 8;
                bool p = (m0 + row < M) && (gk < K);
                long off = (long)(m0 + row) * K + gk;
                uint32_t dst = sB + (uint32_t)row * 64u + (uint32_t)((g ^ ((row >> 1) & 3)) << 4);
                cp_async16(dst,         Ah + off, p);
                cp_async16(dst + 8192u, Al + off, p);
            }
#pragma unroll
            for (int u = 0; u < 2; u++) {
                int idx = u * 128 + tid;
                int row = idx >> 3, g = idx & 7;
                int gk = kt * 32 + row;
                int gn = n0 + g * 8;
                bool p = (gk < K) && (gn < N);
                long off = (long)gk * N + gn;
                uint32_t gs = (uint32_t)g ^ ((uint32_t)row & 7u);
                uint32_t dst = sB + 16384u + (uint32_t)row * 128u + (gs << 4);
                cp_async16(dst,         Bh + off, p);
                cp_async16(dst + 4096u, Bl + off, p);
            }
        }
        CP_COMMIT();
    };

    float acc[4][4][4];
#pragma unroll
    for (int i = 0; i < 4; i++)
#pragma unroll
        for (int j = 0; j < 4; j++)
#pragma unroll
            for (int e = 0; e < 4; e++) acc[i][j][e] = 0.f;

    issue(0); issue(1);

    for (int t = 0; t < nkt; t++) {
        CP_WAIT1();
        __syncthreads();
        issue(t + 2);
        uint32_t aB = sbase + (uint32_t)(t % NSTAGE) * STAGE_BYTES;
        uint32_t bB = aB + 16384u;
#pragma unroll
        for (int ks = 0; ks < 2; ks++) {
            uint32_t ah[4][4], al[4][4], bh4[2][4], bl4[2][4];
#pragma unroll
            for (int i = 0; i < 4; i++) {
                uint32_t row = (uint32_t)(wm * 64 + i * 16 + (lane & 15));
                uint32_t lg = (uint32_t)(ks * 2) + ((uint32_t)lane >> 4);
                uint32_t addr = aB + row * 64u + ((lg ^ ((row >> 1) & 3u)) << 4);
                LDSM_X4(ah[i], addr);
                LDSM_X4(al[i], addr + 8192u);
            }
#pragma unroll
            for (int j2 = 0; j2 < 2; j2++) {
                uint32_t row = (uint32_t)(ks * 16) + (((uint32_t)lane >> 3) & 1u) * 8u + ((uint32_t)lane & 7u);
                uint32_t g = (uint32_t)(wn * 4 + j2 * 2) + ((uint32_t)lane >> 4);
                uint32_t gs = g ^ (row & 7u);
                uint32_t addr = bB + row * 128u + (gs << 4);
                LDSM_X4_T(bh4[j2], addr);
                LDSM_X4_T(bl4[j2], addr + 4096u);
            }
#pragma unroll
            for (int i = 0; i < 4; i++)
#pragma unroll
                for (int j = 0; j < 4; j++) {
                    uint32_t* bh = &bh4[j >> 1][(j & 1) * 2];
                    uint32_t* bl = &bl4[j >> 1][(j & 1) * 2];
                    MMA_BF16(acc[i][j], ah[i], bh);
                    MMA_BF16(acc[i][j], ah[i], bl);
                    MMA_BF16(acc[i][j], al[i], bh);
                }
        }
    }

#pragma unroll
    for (int i = 0; i < 4; i++) {
#pragma unroll
        for (int j = 0; j < 4; j++) {
            int gc = n0 + wn * 32 + j * 8 + (lane & 3) * 2;
            float b0v = 0.f, b1v = 0.f;
            if (bias && gc + 1 < N) { b0v = bias[gc]; b1v = bias[gc + 1]; }
#pragma unroll
            for (int half = 0; half < 2; half++) {
                int gr = m0 + wm * 64 + i * 16 + (lane >> 2) + half * 8;
                if (gr >= M || gc + 1 >= N) continue;
                float v0 = acc[i][j][half * 2 + 0] + b0v;
                float v1 = acc[i][j][half * 2 + 1] + b1v;
                if (mode & 1) {
                    v0 = v0 / (1.f + __expf(-v0));
                    v1 = v1 / (1.f + __expf(-v1));
                }
                long off = (long)gr * N + gc;
                if (mode & 2) {
                    uint32_t hi, lo;
                    split2(v0, v1, hi, lo);
                    *(uint32_t*)&Ch[off] = hi;
                    *(uint32_t*)&Cl[off] = lo;
                } else {
                    *(float2*)&C[off] = make_float2(v0, v1);
                }
            }
        }
    }
}

// ====== tensor-core flash attention: Q planes, bulk cp.async K/V ======
// outmode: 0 write fp32 Out; 1 accumulate into fp32 Out;
//          2 read fp32 Out, add, write transposed [B,T,C] bf16 planes Oh/Ol.
#define ATTN_SMEM_BYTES 65536

__global__ __launch_bounds__(128, 1) void attn_mma_kernel(
    const __nv_bfloat16* __restrict__ Qh, const __nv_bfloat16* __restrict__ Ql,
    const __nv_bfloat16* __restrict__ Kh, const __nv_bfloat16* __restrict__ Kl,
    const __nv_bfloat16* __restrict__ Vh, const __nv_bfloat16* __restrict__ Vl,
    float* __restrict__ Out, __nv_bfloat16* __restrict__ Oh, __nv_bfloat16* __restrict__ Ol,
    int H, int Tq, int Tk,
    long kvbs, long kvhs, int causal, const float* __restrict__ gatep, int outmode)
{
    extern __shared__ __align__(128) unsigned char smem[];
    const uint32_t sb = smem_u32(smem);
    const int tid = threadIdx.x, lane = tid & 31, warp = tid >> 5;
    const int q0 = blockIdx.x * 64, h = blockIdx.y, b = blockIdx.z;
    const long qbase = ((long)(b * H + h)) * Tq * 128;
    const long kbase = (long)b * kvbs + (long)h * kvhs;
    const int qw = q0 + warp * 16;
    const int r0 = lane >> 2;
    const int c2 = (lane & 3) * 2;
    const uint32_t ln7 = lane & 7u;

    uint32_t qh[8][4], ql[8][4];
    {
        long ob0 = qbase + (long)(qw + r0) * 128;
        long ob1 = ob0 + 8 * 128;
#pragma unroll
        for (int kc = 0; kc < 8; kc++) {
            int cc0 = kc * 16 + c2, cc1 = kc * 16 + c2 + 8;
            qh[kc][0] = *(const uint32_t*)&Qh[ob0 + cc0];
            qh[kc][1] = *(const uint32_t*)&Qh[ob1 + cc0];
            qh[kc][2] = *(const uint32_t*)&Qh[ob0 + cc1];
            qh[kc][3] = *(const uint32_t*)&Qh[ob1 + cc1];
            ql[kc][0] = *(const uint32_t*)&Ql[ob0 + cc0];
            ql[kc][1] = *(const uint32_t*)&Ql[ob1 + cc0];
            ql[kc][2] = *(const uint32_t*)&Ql[ob0 + cc1];
            ql[kc][3] = *(const uint32_t*)&Ql[ob1 + cc1];
        }
    }

    float o[16][4];
#pragma unroll
    for (int n = 0; n < 16; n++)
#pragma unroll
        for (int e = 0; e < 4; e++) o[n][e] = 0.f;
    float m0v = -1e30f, m1v = -1e30f, l0v = 0.f, l1v = 0.f;

    const int kend = causal ? min(Tk, q0 + 64) : Tk;

    for (int kt = 0; kt < kend; kt += 64) {
        __syncthreads();
#pragma unroll
        for (int u = 0; u < 8; u++) {
            int idx = u * 128 + tid;
            int r = idx >> 4, g = idx & 15;
            bool p = (kt + r < Tk);
            long off = kbase + (long)(kt + r) * 128 + g * 8;
            uint32_t gs = ((uint32_t)g & 8u) | (((uint32_t)g & 7u) ^ ((uint32_t)r & 7u));
            uint32_t dst = sb + (uint32_t)r * 256u + (gs << 4);
            cp_async16(dst,          Kh + off, p);
            cp_async16(dst + 16384u, Kl + off, p);
            cp_async16(dst + 32768u, Vh + off, p);
            cp_async16(dst + 49152u, Vl + off, p);
        }
        CP_COMMIT();
        CP_WAIT0();
        __syncthreads();

        float s[8][4];
#pragma unroll
        for (int n = 0; n < 8; n++)
#pragma unroll
            for (int e = 0; e < 4; e++) s[n][e] = 0.f;

#pragma unroll
        for (int kc2 = 0; kc2 < 4; kc2++) {
#pragma unroll
            for (int nc = 0; nc < 8; nc++) {
                uint32_t row = (uint32_t)(nc * 8) + ln7;
                uint32_t g = (uint32_t)(kc2 * 4) + (uint32_t)(lane >> 3);
                uint32_t gs = (g & 8u) | ((g & 7u) ^ (row & 7u));
                uint32_t addr = sb + row * 256u + gs * 16u;
                uint32_t kh4[4], kl4[4];
                LDSM_X4(kh4, addr);
                LDSM_X4(kl4, addr + 16384u);
                MMA_BF16(s[nc], qh[2 * kc2],     &kh4[0]);
                MMA_BF16(s[nc], ql[2 * kc2],     &kh4[0]);
                MMA_BF16(s[nc], qh[2 * kc2],     &kl4[0]);
                MMA_BF16(s[nc], qh[2 * kc2 + 1], &kh4[2]);
                MMA_BF16(s[nc], ql[2 * kc2 + 1], &kh4[2]);
                MMA_BF16(s[nc], qh[2 * kc2 + 1], &kl4[2]);
            }
        }

#pragma unroll
        for (int nc = 0; nc < 8; nc++) {
#pragma unroll
            for (int e = 0; e < 4; e++) s[nc][e] *= ATT_SCALE;
        }

        if ((kt + 64 > Tk) || (causal && (kt + 63 >= qw))) {
#pragma unroll
            for (int nc = 0; nc < 8; nc++) {
#pragma unroll
                for (int e = 0; e < 4; e++) {
                    int kk = kt + nc * 8 + c2 + (e & 1);
                    int qr = qw + r0 + ((e >= 2) ? 8 : 0);
                    if (kk >= Tk || (causal && kk > qr)) s[nc][e] = -1e30f;
                }
            }
        }

        float mt0 = -1e30f, mt1 = -1e30f;
#pragma unroll
        for (int nc = 0; nc < 8; nc++) {
            mt0 = fmaxf(mt0, fmaxf(s[nc][0], s[nc][1]));
            mt1 = fmaxf(mt1, fmaxf(s[nc][2], s[nc][3]));
        }
        mt0 = fmaxf(mt0, __shfl_xor_sync(0xffffffffu, mt0, 1));
        mt0 = fmaxf(mt0, __shfl_xor_sync(0xffffffffu, mt0, 2));
        mt1 = fmaxf(mt1, __shfl_xor_sync(0xffffffffu, mt1, 1));
        mt1 = fmaxf(mt1, __shfl_xor_sync(0xffffffffu, mt1, 2));
        float mn0 = fmaxf(m0v, mt0), mn1 = fmaxf(m1v, mt1);
        float corr0 = __expf(m0v - mn0), corr1 = __expf(m1v - mn1);
        m0v = mn0; m1v = mn1;

        uint32_t ph[4][4], pl[4][4];
        float ps0 = 0.f, ps1 = 0.f;
#pragma unroll
        for (int nc = 0; nc < 8; nc++) {
            float p0 = __expf(s[nc][0] - mn0);
            float p1 = __expf(s[nc][1] - mn0);
            float p2 = __expf(s[nc][2] - mn1);
            float p3 = __expf(s[nc][3] - mn1);
            ps0 += p0 + p1; ps1 += p2 + p3;
            uint32_t h01, l01, h23, l23;
            split2(p0, p1, h01, l01);
            split2(p2, p3, h23, l23);
            int kc = nc >> 1;
            if ((nc & 1) == 0) { ph[kc][0] = h01; ph[kc][1] = h23; pl[kc][0] = l01; pl[kc][1] = l23; }
            else               { ph[kc][2] = h01; ph[kc][3] = h23; pl[kc][2] = l01; pl[kc][3] = l23; }
        }
        ps0 += __shfl_xor_sync(0xffffffffu, ps0, 1);
        ps0 += __shfl_xor_sync(0xffffffffu, ps0, 2);
        ps1 += __shfl_xor_sync(0xffffffffu, ps1, 1);
        ps1 += __shfl_xor_sync(0xffffffffu, ps1, 2);
        l0v = l0v * corr0 + ps0;
        l1v = l1v * corr1 + ps1;

#pragma unroll
        for (int n = 0; n < 16; n++) {
            o[n][0] *= corr0; o[n][1] *= corr0;
            o[n][2] *= corr1; o[n][3] *= corr1;
        }

#pragma unroll
        for (int kc = 0; kc < 4; kc++) {
            uint32_t row = (uint32_t)(kc * 16) + ((uint32_t)((lane >> 3) & 1)) * 8u + ln7;
#pragma unroll
            for (int dp = 0; dp < 8; dp++) {
                uint32_t g = (uint32_t)(dp * 2) + (uint32_t)(lane >> 4);
                uint32_t gs = (g & 8u) | ((g & 7u) ^ (row & 7u));
                uint32_t addr = sb + 32768u + row * 256u + gs * 16u;
                uint32_t vh4[4], vl4[4];
                LDSM_X4_T(vh4, addr);
                LDSM_X4_T(vl4, addr + 16384u);
                MMA_BF16(o[2 * dp],     ph[kc], &vh4[0]);
                MMA_BF16(o[2 * dp],     pl[kc], &vh4[0]);
                MMA_BF16(o[2 * dp],     ph[kc], &vl4[0]);
                MMA_BF16(o[2 * dp + 1], ph[kc], &vh4[2]);
                MMA_BF16(o[2 * dp + 1], pl[kc], &vh4[2]);
                MMA_BF16(o[2 * dp + 1], ph[kc], &vl4[2]);
            }
        }
    }

    float gate = gatep ? *gatep : 1.f;
    float sc0 = gate / l0v, sc1 = gate / l1v;
#pragma unroll
    for (int n = 0; n < 16; n++) {
        int gc = n * 8 + c2;
        long off0 = qbase + (long)(qw + r0) * 128 + gc;
        long off1 = off0 + 8 * 128;
        float2 v0 = make_float2(o[n][0] * sc0, o[n][1] * sc0);
        float2 v1 = make_float2(o[n][2] * sc1, o[n][3] * sc1);
        if (outmode >= 1) {
            float2 p0 = *(const float2*)&Out[off0];
            float2 p1 = *(const float2*)&Out[off1];
            v0.x += p0.x; v0.y += p0.y;
            v1.x += p1.x; v1.y += p1.y;
        }
        if (outmode == 2) {
            long offT0 = ((long)b * Tq + qw + r0) * (long)(H * 128) + (long)h * 128 + gc;
            long offT1 = offT0 + (long)8 * (H * 128);
            uint32_t hi, lo;
            split2(v0.x, v0.y, hi, lo);
            *(uint32_t*)&Oh[offT0] = hi;
            *(uint32_t*)&Ol[offT0] = lo;
            split2(v1.x, v1.y, hi, lo);
            *(uint32_t*)&Oh[offT1] = hi;
            *(uint32_t*)&Ol[offT1] = lo;
        } else {
            *(float2*)&Out[off0] = v0;
            *(float2*)&Out[off1] = v1;
        }
    }
}

// ================= rmsnorm per row -> bf16 planes =================
__global__ void rmsnorm_planes_kernel(const float* __restrict__ in, const float* __restrict__ w,
                                      __nv_bfloat16* __restrict__ oh, __nv_bfloat16* __restrict__ ol,
                                      int N)
{
    int row = blockIdx.x;
    const float* x = in + (long)row * N;
    float ss = 0.f;
    for (int c = threadIdx.x; c < N; c += 256) { float v = x[c]; ss = fmaf(v, v, ss); }
    __shared__ float sh[32];
    int lane = threadIdx.x & 31, wid = threadIdx.x >> 5;
#pragma unroll
    for (int o = 16; o; o >>= 1) ss += __shfl_xor_sync(0xffffffffu, ss, o);
    if (lane == 0) sh[wid] = ss;
    __syncthreads();
    float tot = (threadIdx.x < 8) ? sh[threadIdx.x] : 0.f;
    if (wid == 0) {
#pragma unroll
        for (int o = 16; o; o >>= 1) tot += __shfl_xor_sync(0xffffffffu, tot, o);
    }
    __shared__ float ssc;
    if (threadIdx.x == 0) ssc = rsqrtf(tot / (float)N + 1e-5f);
    __syncthreads();
    float sc = ssc;
    for (int c = threadIdx.x * 2; c < N; c += 512) {
        float v0 = x[c] * sc * w[c];
        float v1 = x[c + 1] * sc * w[c + 1];
        uint32_t hi, lo;
        split2(v0, v1, hi, lo);
        *(uint32_t*)&oh[(long)row * N + c] = hi;
        *(uint32_t*)&ol[(long)row * N + c] = lo;
    }
}

// ===== split qkv + rope -> q/k/v planes =====
__global__ void split_rope_kernel(const float* __restrict__ qkv,
                                  const float* __restrict__ cos_, const float* __restrict__ sin_,
                                  __nv_bfloat16* __restrict__ qh, __nv_bfloat16* __restrict__ qlp,
                                  __nv_bfloat16* __restrict__ kh, __nv_bfloat16* __restrict__ kl,
                                  __nv_bfloat16* __restrict__ vh, __nv_bfloat16* __restrict__ vl)
{
    int idx = blockIdx.x * blockDim.x + threadIdx.x;
    if (idx >= BB * TT * NH * 64) return;
    int i = idx & 63;
    int h = (idx >> 6) & 31;
    int t = (idx >> 11) & 1023;
    int b = idx >> 21;
    long base = ((long)(b * TT + t)) * (3 * CC) + h * HS + 2 * i;
    float q0 = qkv[base],        q1 = qkv[base + 1];
    float k0 = qkv[base + CC],   k1 = qkv[base + CC + 1];
    float v0 = qkv[base + 2*CC], v1 = qkv[base + 2*CC + 1];
    float c = cos_[t * 64 + i], s = sin_[t * 64 + i];
    long ob = ((long)((b * NH + h) * TT + t)) * HS + 2 * i;
    uint32_t hi, lo;
    split2(q0 * c - q1 * s, q1 * c + q0 * s, hi, lo);
    *(uint32_t*)&qh[ob] = hi;
    *(uint32_t*)&qlp[ob] = lo;
    split2(k0 * c - k1 * s, k1 * c + k0 * s, hi, lo);
    *(uint32_t*)&kh[ob] = hi;
    *(uint32_t*)&kl[ob] = lo;
    split2(v0, v1, hi, lo);
    *(uint32_t*)&vh[ob] = hi;
    *(uint32_t*)&vl[ob] = lo;
}

// ================= adapter split -> planes =================
__global__ void adapter_split_kernel(const float* __restrict__ aqkv,
                                     __nv_bfloat16* __restrict__ akh, __nv_bfloat16* __restrict__ akl,
                                     __nv_bfloat16* __restrict__ avh, __nv_bfloat16* __restrict__ avl)
{
    int idx2 = blockIdx.x * blockDim.x + threadIdx.x;
    if (idx2 >= NH * ALEN * HS / 2) return;
    int idx = idx2 * 2;
    int d = idx & 127;
    int a = (idx >> 7) % ALEN;
    int h = idx / (ALEN * HS);
    long src = (long)a * (3 * CC) + h * HS + d;
    uint32_t hi, lo;
    split2(aqkv[src + CC], aqkv[src + CC + 1], hi, lo);
    *(uint32_t*)&akh[idx] = hi;
    *(uint32_t*)&akl[idx] = lo;
    split2(aqkv[src + 2*CC], aqkv[src + 2*CC + 1], hi, lo);
    *(uint32_t*)&avh[idx] = hi;
    *(uint32_t*)&avl[idx] = lo;
}

// ================= assemble pk/pv -> planes =================
__global__ void fill_pkv_kernel(const float* __restrict__ wflat, const float* __restrict__ pad,
                                __nv_bfloat16* __restrict__ ph, __nv_bfloat16* __restrict__ pl)
{
    int idx2 = blockIdx.x * blockDim.x + threadIdx.x;
    if (idx2 >= BB * NH * AT * HS / 2) return;
    int idx = idx2 * 2;
    int d = idx & 127;
    int t = (idx >> 7) % AT;
    int h = (idx / (HS * AT)) & 31;
    int b = idx / (HS * AT * NH);
    float v0, v1;
    if (h < NWH && d < WHD) {
        long src = (long)b * (AT * AD) + h * (AT * WHD) + t * WHD + d;
        v0 = wflat[src]; v1 = wflat[src + 1];
    } else {
        long src = ((long)b * AT + t) * HS + d;
        v0 = pad[src]; v1 = pad[src + 1];
    }
    uint32_t hi, lo;
    split2(v0, v1, hi, lo);
    *(uint32_t*)&ph[idx] = hi;
    *(uint32_t*)&pl[idx] = lo;
}

// ================= head mix -> q2 planes =================
__global__ __launch_bounds__(256) void headmix_kernel(const float* __restrict__ q2a,
                                                      const float* __restrict__ w,
                                                      __nv_bfloat16* __restrict__ q2h,
                                                      __nv_bfloat16* __restrict__ q2l)
{
    int bt = blockIdx.x;
    int b = bt >> 10, t = bt & 1023;
    __shared__ float sm[NH * HS];
    __shared__ float ws[NH * NH];
    for (int i = threadIdx.x; i < NH * HS; i += 256) {
        int h = i >> 7, d = i & 127;
        sm[i] = q2a[(((long)(b * NH + h)) * TT + t) * HS + d];
    }
    for (int i = threadIdx.x; i < NH * NH; i += 256) ws[i] = w[i];
    __syncthreads();
    for (int i2 = threadIdx.x; i2 < NH * HS / 2; i2 += 256) {
        int i = i2 * 2;
        int g = i >> 7, d = i & 127;
        float acc0 = 0.f, acc1 = 0.f;
#pragma unroll
        for (int h = 0; h < NH; h++) {
            float wv = ws[h * NH + g];
            acc0 = fmaf(sm[h * HS + d],     wv, acc0);
            acc1 = fmaf(sm[h * HS + d + 1], wv, acc1);
        }
        long dst = (((long)(b * NH + g)) * TT + t) * HS + d;
        uint32_t hi, lo;
        split2(acc0, acc1, hi, lo);
        *(uint32_t*)&q2h[dst] = hi;
        *(uint32_t*)&q2l[dst] = lo;
    }
}

// ================= host launcher =================
static float* symp(const void* symbol)
{
    void* p = nullptr;
    cudaGetSymbolAddress(&p, symbol);
    return (float*)p;
}
static __nv_bfloat16* symb(const void* symbol)
{
    void* p = nullptr;
    cudaGetSymbolAddress(&p, symbol);
    return (__nv_bfloat16*)p;
}

static inline void gemm_pl(const __nv_bfloat16* Ah, const __nv_bfloat16* Al,
                           const __nv_bfloat16* Bh, const __nv_bfloat16* Bl,
                           float* C, __nv_bfloat16* Ch, __nv_bfloat16* Cl,
                           int M, int N, int K, const float* bias, int mode)
{
    dim3 grid((M + 127) / 128, (N + 63) / 64);
    gemm_planes_kernel<<<grid, 128, GEMM_SMEM_BYTES>>>(Ah, Al, Bh, Bl, C, Ch, Cl, M, N, K, bias, mode);
}

static inline void convert(const float* in, __nv_bfloat16* h, __nv_bfloat16* l, long n)
{
    int n8 = (int)(n / 8);
    convert_kernel<<<(n8 + 255) / 256, 256>>>(in, h, l, n8);
}

extern "C" void kernel_launch(void* const* d_in, const int* in_sizes, int n_in,
                              void* d_out, int out_size)
{
    (void)in_sizes; (void)n_in; (void)out_size;
    const float* x        = (const float*)d_in[0];
    const float* audio    = (const float*)d_in[1];
    const float* rope_cos = (const float*)d_in[2];
    const float* rope_sin = (const float*)d_in[3];
    const float* pad_k    = (const float*)d_in[6];
    const float* pad_v    = (const float*)d_in[7];
    const float* c_attn_w = (const float*)d_in[8];
    const float* c_proj_w = (const float*)d_in[9];
    const float* adapter  = (const float*)d_in[10];
    const float* gating   = (const float*)d_in[11];
    const float* rms_gate = (const float*)d_in[12];
    const float* rms_key  = (const float*)d_in[13];
    const float* rms_val  = (const float*)d_in[14];
    const float* proj_dn  = (const float*)d_in[15];
    const float* proj_up  = (const float*)d_in[16];
    const float* pq128    = (const float*)d_in[17];
    const float* pq32     = (const float*)d_in[18];
    const float* pgating  = (const float*)d_in[19];
    const float* wkw      = (const float*)d_in[20];
    const float* wvw      = (const float*)d_in[21];
    const float* wvb      = (const float*)d_in[22];
    float* out = (float*)d_out;

    float *qkv = symp(g_qkv), *y = symp(g_y);
    float *aqkv = symp(g_aqkv);
    float *wkn = symp(g_wkn), *wvn = symp(g_wvn), *wk = symp(g_wk), *wv = symp(g_wv);
    float *q2a = symp(g_q2a);

    __nv_bfloat16 *xh = symb(g_xh), *xl = symb(g_xl);
    __nv_bfloat16 *awh = symb(g_awh), *awl = symb(g_awl);
    __nv_bfloat16 *pwh = symb(g_pwh), *pwl = symb(g_pwl);
    __nv_bfloat16 *audh = symb(g_audh), *audl = symb(g_audl);
    __nv_bfloat16 *wkwh = symb(g_wkwh), *wkwl = symb(g_wkwl);
    __nv_bfloat16 *wvwh = symb(g_wvwh), *wvwl = symb(g_wvwl);
    __nv_bfloat16 *pdnh = symb(g_pdnh), *pdnl = symb(g_pdnl);
    __nv_bfloat16 *puph = symb(g_puph), *pupl = symb(g_pupl);
    __nv_bfloat16 *pqh = symb(g_pqh), *pql = symb(g_pql);
    __nv_bfloat16 *qph = symb(g_qph), *qpl = symb(g_qpl);
    __nv_bfloat16 *q2h = symb(g_q2h), *q2l = symb(g_q2l);
    __nv_bfloat16 *prefh = symb(g_prefh), *prefl = symb(g_prefl);
    __nv_bfloat16 *wknh = symb(g_wknh), *wknl = symb(g_wknl);
    __nv_bfloat16 *wvnh = symb(g_wvnh), *wvnl = symb(g_wvnl);
    __nv_bfloat16 *hidh = symb(g_hidh), *hidl = symb(g_hidl);
    __nv_bfloat16 *ybth = symb(g_ybth), *ybtl = symb(g_ybtl);
    __nv_bfloat16 *kh = symb(g_kh), *kl = symb(g_kl), *vh = symb(g_vh), *vl = symb(g_vl);
    __nv_bfloat16 *akh = symb(g_akh), *akl = symb(g_akl), *avh = symb(g_avh), *avl = symb(g_avl);
    __nv_bfloat16 *pkh = symb(g_pkh), *pkl = symb(g_pkl), *pvh = symb(g_pvh), *pvl = symb(g_pvl);

    cudaFuncSetAttribute(gemm_planes_kernel, cudaFuncAttributeMaxDynamicSharedMemorySize,
                         GEMM_SMEM_BYTES);
    cudaFuncSetAttribute(attn_mma_kernel, cudaFuncAttributeMaxDynamicSharedMemorySize,
                         ATTN_SMEM_BYTES);

    const int M = BB * TT;            // 2048
    const int MA = BB * AT;           // 3000

    // 0) operand conversions
    convert(x, xh, xl, (long)BB*TT*CC);
    convert(c_attn_w, awh, awl, (long)CC*3*CC);
    convert(c_proj_w, pwh, pwl, (long)CC*CC);
    convert(audio, audh, audl, (long)BB*AT*AD);
    convert(wkw, wkwh, wkwl, (long)AD*AD);
    convert(wvw, wvwh, wvwl, (long)AD*AD);
    convert(proj_dn, pdnh, pdnl, (long)AD*DHID);
    convert(proj_up, puph, pupl, (long)DHID*AD);
    convert(pq128, pqh, pql, (long)HS*HS);

    // 1) qkv = x @ c_attn_w
    gemm_pl(xh, xl, awh, awl, qkv, nullptr, nullptr, M, 3*CC, CC, nullptr, 0);

    // 2) split + rope -> q/k/v planes
    {
        int tot = BB * TT * NH * 64;
        split_rope_kernel<<<(tot + 255) / 256, 256>>>(qkv, rope_cos, rope_sin,
                                                      qph, qpl, kh, kl, vh, vl);
    }

    // 3) causal self-attention -> y
    attn_mma_kernel<<<dim3(TT/64, NH, BB), 128, ATTN_SMEM_BYTES>>>(
        qph, qpl, kh, kl, vh, vl, y, nullptr, nullptr,
        NH, TT, TT, (long)NH*TT*HS, (long)TT*HS, 1, nullptr, 0);

    // 4) adapter branch
    rmsnorm_planes_kernel<<<ALEN, 256>>>(adapter, rms_gate, prefh, prefl, CC);
    gemm_pl(prefh, prefl, awh, awl, aqkv, nullptr, nullptr, ALEN, 3*CC, CC, nullptr, 0);
    adapter_split_kernel<<<(NH*ALEN*HS/2 + 255) / 256, 256>>>(aqkv, akh, akl, avh, avl);
    attn_mma_kernel<<<dim3(TT/64, NH, BB), 128, ATTN_SMEM_BYTES>>>(
        qph, qpl, akh, akl, avh, avl, y, nullptr, nullptr,
        NH, TT, ALEN, 0L, (long)ALEN*HS, 0, gating, 1);

    // 5) whisper key path
    gemm_pl(audh, audl, wkwh, wkwl, wkn, nullptr, nullptr, MA, AD, AD, nullptr, 0);
    rmsnorm_planes_kernel<<<MA, 256>>>(wkn, rms_key, wknh, wknl, AD);
    gemm_pl(wknh, wknl, pdnh, pdnl, nullptr, hidh, hidl, MA, DHID, AD, nullptr, 3);
    gemm_pl(hidh, hidl, puph, pupl, wk, nullptr, nullptr, MA, AD, DHID, nullptr, 0);

    // 6) whisper value path
    gemm_pl(audh, audl, wvwh, wvwl, wvn, nullptr, nullptr, MA, AD, AD, wvb, 0);
    rmsnorm_planes_kernel<<<MA, 256>>>(wvn, rms_val, wvnh, wvnl, AD);
    gemm_pl(wvnh, wvnl, pdnh, pdnl, nullptr, hidh, hidl, MA, DHID, AD, nullptr, 3);
    gemm_pl(hidh, hidl, puph, pupl, wv, nullptr, nullptr, MA, AD, DHID, nullptr, 0);

    // 7) assemble pk/pv planes
    {
        int tot2 = BB * NH * AT * HS / 2;
        fill_pkv_kernel<<<(tot2 + 255) / 256, 256>>>(wk, pad_k, pkh, pkl);
        fill_pkv_kernel<<<(tot2 + 255) / 256, 256>>>(wv, pad_v, pvh, pvl);
    }

    // 8) q2 = (q @ proj_q128) head-mixed by proj_q32 -> planes
    gemm_pl(qph, qpl, pqh, pql, q2a, nullptr, nullptr, BB*NH*TT, HS, HS, nullptr, 0);
    headmix_kernel<<<BB * TT, 256>>>(q2a, pq32, q2h, q2l);

    // 9) whisper cross-attention -> fused accumulate + transpose -> ybt planes
    attn_mma_kernel<<<dim3(TT/64, NH, BB), 128, ATTN_SMEM_BYTES>>>(
        q2h, q2l, pkh, pkl, pvh, pvl, y, ybth, ybtl,
        NH, TT, AT, (long)NH*AT*HS, (long)AT*HS, 0, pgating, 2);

    // 10) output projection
    gemm_pl(ybth, ybtl, pwh, pwl, out, nullptr, nullptr, M, CC, CC, nullptr, 0);
}

// round 15
// speedup vs baseline: 1.0374x; 1.0215x over previous
#include <cuda_runtime.h>
#include <cuda_bf16.h>
#include <math.h>
#include <stdint.h>

// ---------------- problem constants ----------------
#define BB 2
#define TT 1024
#define CC 4096
#define NH 32
#define HS 128
#define ALEN 10
#define AT 1500
#define AD 1280
#define NWH 20
#define WHD 64
#define DHID 80           // AD/16
#define ATT_SCALE 0.08838834764831845f   // 1/sqrt(128)
#define MFUSE (BB*TT + ALEN)             // 2058: x rows + adapter rows

// ---------------- fp32 scratch ----------------
__device__ float g_qkv [(long)MFUSE*3*CC];
__device__ float g_y   [BB*NH*TT*HS];
__device__ float g_wkn [BB*AT*AD];
__device__ float g_wvn [BB*AT*AD];
__device__ float g_wk  [BB*AT*AD];
__device__ float g_wv  [BB*AT*AD];
__device__ float g_q2a [BB*NH*TT*HS];

// ---------------- bf16 hi/lo plane scratch ----------------
__device__ __nv_bfloat16 g_xh[(long)MFUSE*CC], g_xl[(long)MFUSE*CC];   // x rows + pref rows
__device__ __nv_bfloat16 g_awh[CC*3*CC],    g_awl[CC*3*CC];
__device__ __nv_bfloat16 g_pwh[CC*CC],      g_pwl[CC*CC];
__device__ __nv_bfloat16 g_audh[BB*AT*AD],  g_audl[BB*AT*AD];
__device__ __nv_bfloat16 g_wkwh[AD*AD],     g_wkwl[AD*AD];
__device__ __nv_bfloat16 g_wvwh[AD*AD],     g_wvwl[AD*AD];
__device__ __nv_bfloat16 g_pdnh[AD*DHID],   g_pdnl[AD*DHID];
__device__ __nv_bfloat16 g_puph[DHID*AD],   g_pupl[DHID*AD];
__device__ __nv_bfloat16 g_pqh[HS*HS],      g_pql[HS*HS];
__device__ __nv_bfloat16 g_qph[BB*NH*TT*HS],g_qpl[BB*NH*TT*HS];
__device__ __nv_bfloat16 g_q2h[BB*NH*TT*HS],g_q2l[BB*NH*TT*HS];
__device__ __nv_bfloat16 g_wknh[BB*AT*AD],  g_wknl[BB*AT*AD];
__device__ __nv_bfloat16 g_wvnh[BB*AT*AD],  g_wvnl[BB*AT*AD];
__device__ __nv_bfloat16 g_hidh[BB*AT*DHID],g_hidl[BB*AT*DHID];
__device__ __nv_bfloat16 g_ybth[BB*TT*CC],  g_ybtl[BB*TT*CC];
// attention K/V planes
__device__ __nv_bfloat16 g_kh[BB*NH*TT*HS], g_kl[BB*NH*TT*HS];
__device__ __nv_bfloat16 g_vh[BB*NH*TT*HS], g_vl[BB*NH*TT*HS];
__device__ __nv_bfloat16 g_akh[NH*ALEN*HS], g_akl[NH*ALEN*HS];
__device__ __nv_bfloat16 g_avh[NH*ALEN*HS], g_avl[NH*ALEN*HS];
__device__ __nv_bfloat16 g_pkh[BB*NH*AT*HS],g_pkl[BB*NH*AT*HS];
__device__ __nv_bfloat16 g_pvh[BB*NH*AT*HS],g_pvl[BB*NH*AT*HS];

// ================= helpers =================
__device__ __forceinline__ uint32_t smem_u32(const void* p) {
    uint32_t a;
    asm("{ .reg .u64 t; cvta.to.shared.u64 t, %1; cvt.u32.u64 %0, t; }" : "=r"(a) : "l"(p));
    return a;
}

#define LDSM_X4(r, addr) \
    asm volatile("ldmatrix.sync.aligned.m8n8.x4.shared.b16 {%0,%1,%2,%3}, [%4];" \
        : "=r"((r)[0]), "=r"((r)[1]), "=r"((r)[2]), "=r"((r)[3]) : "r"(addr))
#define LDSM_X4_T(r, addr) \
    asm volatile("ldmatrix.sync.aligned.m8n8.x4.trans.shared.b16 {%0,%1,%2,%3}, [%4];" \
        : "=r"((r)[0]), "=r"((r)[1]), "=r"((r)[2]), "=r"((r)[3]) : "r"(addr))
#define MMA_BF16(c, a, b) \
    asm volatile("mma.sync.aligned.m16n8k16.row.col.f32.bf16.bf16.f32 " \
        "{%0,%1,%2,%3}, {%4,%5,%6,%7}, {%8,%9}, {%0,%1,%2,%3};" \
        : "+f"((c)[0]), "+f"((c)[1]), "+f"((c)[2]), "+f"((c)[3]) \
        : "r"((a)[0]), "r"((a)[1]), "r"((a)[2]), "r"((a)[3]), "r"((b)[0]), "r"((b)[1]))

__device__ __forceinline__ void cp_async16(uint32_t dst, const void* src, bool pred) {
    int sz = pred ? 16 : 0;
    asm volatile("cp.async.cg.shared.global [%0], [%1], 16, %2;"
                 :: "r"(dst), "l"(src), "r"(sz) : "memory");
}
#define CP_COMMIT() asm volatile("cp.async.commit_group;" ::: "memory")
#define CP_WAIT1()  asm volatile("cp.async.wait_group 1;"  ::: "memory")
#define CP_WAIT0()  asm volatile("cp.async.wait_group 0;"  ::: "memory")

__device__ __forceinline__ uint32_t pack_bf2(float a, float b) {
    __nv_bfloat162 t = __floats2bfloat162_rn(a, b);
    return *(uint32_t*)&t;
}
__device__ __forceinline__ void trunc_split4(const float4 v, uint2& hi, uint2& lo) {
    uint32_t x = __float_as_uint(v.x), y = __float_as_uint(v.y);
    uint32_t z = __float_as_uint(v.z), w = __float_as_uint(v.w);
    hi.x = __byte_perm(x, y, 0x7632);
    hi.y = __byte_perm(z, w, 0x7632);
    float r0 = v.x - __uint_as_float(x & 0xffff0000u);
    float r1 = v.y - __uint_as_float(y & 0xffff0000u);
    float r2 = v.z - __uint_as_float(z & 0xffff0000u);
    float r3 = v.w - __uint_as_float(w & 0xffff0000u);
    lo.x = pack_bf2(r0, r1);
    lo.y = pack_bf2(r2, r3);
}
__device__ __forceinline__ void split2(float a, float b, uint32_t& hi, uint32_t& lo) {
    uint32_t ua = __float_as_uint(a), ub = __float_as_uint(b);
    hi = __byte_perm(ua, ub, 0x7632);
    float ra = a - __uint_as_float(ua & 0xffff0000u);
    float rb = b - __uint_as_float(ub & 0xffff0000u);
    lo = pack_bf2(ra, rb);
}

// ======== fp32 -> bf16 plane converter ========
__global__ void convert_kernel(const float* __restrict__ in,
                               __nv_bfloat16* __restrict__ h, __nv_bfloat16* __restrict__ l,
                               int n8)
{
    int i = blockIdx.x * blockDim.x + threadIdx.x;
    if (i >= n8) return;
    float4 a = ((const float4*)in)[i * 2];
    float4 b = ((const float4*)in)[i * 2 + 1];
    uint2 h0, l0, h1, l1;
    trunc_split4(a, h0, l0);
    trunc_split4(b, h1, l1);
    uint4 H = make_uint4(h0.x, h0.y, h1.x, h1.y);
    uint4 L = make_uint4(l0.x, l0.y, l1.x, l1.y);
    ((uint4*)h)[i] = H;
    ((uint4*)l)[i] = L;
}

// ================= plane GEMM, 3 CTAs/SM =================
// mode: bit0 silu; bit1 write bf16 planes (Ch/Cl) instead of fp32 C.
#define NSTAGE 3
#define STAGE_BYTES 24576
#define GEMM_SMEM_BYTES (NSTAGE * STAGE_BYTES)

__global__ __launch_bounds__(128, 3) void gemm_planes_kernel(
    const __nv_bfloat16* __restrict__ Ah, const __nv_bfloat16* __restrict__ Al,
    const __nv_bfloat16* __restrict__ Bh, const __nv_bfloat16* __restrict__ Bl,
    float* __restrict__ C, __nv_bfloat16* __restrict__ Ch, __nv_bfloat16* __restrict__ Cl,
    int M, int N, int K, const float* __restrict__ bias, int mode)
{
    extern __shared__ __align__(128) unsigned char smem[];
    const uint32_t sbase = smem_u32(smem);
    const int tid = threadIdx.x;
    const int lane = tid & 31, warp = tid >> 5;
    const int wm = warp & 1, wn = warp >> 1;
    const int m0 = blockIdx.x * 128, n0 = blockIdx.y * 64;
    const int nkt = (K + 31) / 32;

    auto issue = [&](int t) {
        if (t < nkt) {
            uint32_t sB = sbase + (uint32_t)(t % NSTAGE) * STAGE_BYTES;
            int kt = t;
#pragma unroll
            for (int u = 0; u < 4; u++) {
                int idx = u * 128 + tid;
                int row = idx >> 2, g = idx & 3;
                int gk = kt * 32 + g * 8;
                bool p = (m0 + row < M) && (gk < K);
                long off = (long)(m0 + row) * K + gk;
                uint32_t dst = sB + (uint32_t)row * 64u + (uint32_t)((g ^ ((row >> 1) & 3)) << 4);
                cp_async16(dst,         Ah + off, p);
                cp_async16(dst + 8192u, Al + off, p);
            }
#pragma unroll
            for (int u = 0; u < 2; u++) {
                int idx = u * 128 + tid;
                int row = idx >> 3, g = idx & 7;
                int gk = kt * 32 + row;
                int gn = n0 + g * 8;
                bool p = (gk < K) && (gn < N);
                long off = (long)gk * N + gn;
                uint32_t gs = (uint32_t)g ^ ((uint32_t)row & 7u);
                uint32_t dst = sB + 16384u + (uint32_t)row * 128u + (gs << 4);
                cp_async16(dst,         Bh + off, p);
                cp_async16(dst + 4096u, Bl + off, p);
            }
        }
        CP_COMMIT();
    };

    float acc[4][4][4];
#pragma unroll
    for (int i = 0; i < 4; i++)
#pragma unroll
        for (int j = 0; j < 4; j++)
#pragma unroll
            for (int e = 0; e < 4; e++) acc[i][j][e] = 0.f;

    issue(0); issue(1);

    for (int t = 0; t < nkt; t++) {
        CP_WAIT1();
        __syncthreads();
        issue(t + 2);
        uint32_t aB = sbase + (uint32_t)(t % NSTAGE) * STAGE_BYTES;
        uint32_t bB = aB + 16384u;
#pragma unroll
        for (int ks = 0; ks < 2; ks++) {
            uint32_t ah[4][4], al[4][4], bh4[2][4], bl4[2][4];
#pragma unroll
            for (int i = 0; i < 4; i++) {
                uint32_t row = (uint32_t)(wm * 64 + i * 16 + (lane & 15));
                uint32_t lg = (uint32_t)(ks * 2) + ((uint32_t)lane >> 4);
                uint32_t addr = aB + row * 64u + ((lg ^ ((row >> 1) & 3u)) << 4);
                LDSM_X4(ah[i], addr);
                LDSM_X4(al[i], addr + 8192u);
            }
#pragma unroll
            for (int j2 = 0; j2 < 2; j2++) {
                uint32_t row = (uint32_t)(ks * 16) + (((uint32_t)lane >> 3) & 1u) * 8u + ((uint32_t)lane & 7u);
                uint32_t g = (uint32_t)(wn * 4 + j2 * 2) + ((uint32_t)lane >> 4);
                uint32_t gs = g ^ (row & 7u);
                uint32_t addr = bB + row * 128u + (gs << 4);
                LDSM_X4_T(bh4[j2], addr);
                LDSM_X4_T(bl4[j2], addr + 4096u);
            }
#pragma unroll
            for (int i = 0; i < 4; i++)
#pragma unroll
                for (int j = 0; j < 4; j++) {
                    uint32_t* bh = &bh4[j >> 1][(j & 1) * 2];
                    uint32_t* bl = &bl4[j >> 1][(j & 1) * 2];
                    MMA_BF16(acc[i][j], ah[i], bh);
                    MMA_BF16(acc[i][j], ah[i], bl);
                    MMA_BF16(acc[i][j], al[i], bh);
                }
        }
    }

#pragma unroll
    for (int i = 0; i < 4; i++) {
#pragma unroll
        for (int j = 0; j < 4; j++) {
            int gc = n0 + wn * 32 + j * 8 + (lane & 3) * 2;
            float b0v = 0.f, b1v = 0.f;
            if (bias && gc + 1 < N) { b0v = bias[gc]; b1v = bias[gc + 1]; }
#pragma unroll
            for (int half = 0; half < 2; half++) {
                int gr = m0 + wm * 64 + i * 16 + (lane >> 2) + half * 8;
                if (gr >= M || gc + 1 >= N) continue;
                float v0 = acc[i][j][half * 2 + 0] + b0v;
                float v1 = acc[i][j][half * 2 + 1] + b1v;
                if (mode & 1) {
                    v0 = v0 / (1.f + __expf(-v0));
                    v1 = v1 / (1.f + __expf(-v1));
                }
                long off = (long)gr * N + gc;
                if (mode & 2) {
                    uint32_t hi, lo;
                    split2(v0, v1, hi, lo);
                    *(uint32_t*)&Ch[off] = hi;
                    *(uint32_t*)&Cl[off] = lo;
                } else {
                    *(float2*)&C[off] = make_float2(v0, v1);
                }
            }
        }
    }
}

// ====== tensor-core flash attention: Q planes, bulk cp.async K/V ======
// outmode: 0 write fp32 Out; 1 accumulate into fp32 Out;
//          2 read fp32 Out, add, write transposed [B,T,C] bf16 planes Oh/Ol.
#define ATTN_SMEM_BYTES 65536

__global__ __launch_bounds__(128, 1) void attn_mma_kernel(
    const __nv_bfloat16* __restrict__ Qh, const __nv_bfloat16* __restrict__ Ql,
    const __nv_bfloat16* __restrict__ Kh, const __nv_bfloat16* __restrict__ Kl,
    const __nv_bfloat16* __restrict__ Vh, const __nv_bfloat16* __restrict__ Vl,
    float* __restrict__ Out, __nv_bfloat16* __restrict__ Oh, __nv_bfloat16* __restrict__ Ol,
    int H, int Tq, int Tk,
    long kvbs, long kvhs, int causal, const float* __restrict__ gatep, int outmode)
{
    extern __shared__ __align__(128) unsigned char smem[];
    const uint32_t sb = smem_u32(smem);
    const int tid = threadIdx.x, lane = tid & 31, warp = tid >> 5;
    const int q0 = blockIdx.x * 64, h = blockIdx.y, b = blockIdx.z;
    const long qbase = ((long)(b * H + h)) * Tq * 128;
    const long kbase = (long)b * kvbs + (long)h * kvhs;
    const int qw = q0 + warp * 16;
    const int r0 = lane >> 2;
    const int c2 = (lane & 3) * 2;
    const uint32_t ln7 = lane & 7u;

    uint32_t qh[8][4], ql[8][4];
    {
        long ob0 = qbase + (long)(qw + r0) * 128;
        long ob1 = ob0 + 8 * 128;
#pragma unroll
        for (int kc = 0; kc < 8; kc++) {
            int cc0 = kc * 16 + c2, cc1 = kc * 16 + c2 + 8;
            qh[kc][0] = *(const uint32_t*)&Qh[ob0 + cc0];
            qh[kc][1] = *(const uint32_t*)&Qh[ob1 + cc0];
            qh[kc][2] = *(const uint32_t*)&Qh[ob0 + cc1];
            qh[kc][3] = *(const uint32_t*)&Qh[ob1 + cc1];
            ql[kc][0] = *(const uint32_t*)&Ql[ob0 + cc0];
            ql[kc][1] = *(const uint32_t*)&Ql[ob1 + cc0];
            ql[kc][2] = *(const uint32_t*)&Ql[ob0 + cc1];
            ql[kc][3] = *(const uint32_t*)&Ql[ob1 + cc1];
        }
    }

    float o[16][4];
#pragma unroll
    for (int n = 0; n < 16; n++)
#pragma unroll
        for (int e = 0; e < 4; e++) o[n][e] = 0.f;
    float m0v = -1e30f, m1v = -1e30f, l0v = 0.f, l1v = 0.f;

    const int kend = causal ? min(Tk, q0 + 64) : Tk;

    for (int kt = 0; kt < kend; kt += 64) {
        __syncthreads();
#pragma unroll
        for (int u = 0; u < 8; u++) {
            int idx = u * 128 + tid;
            int r = idx >> 4, g = idx & 15;
            bool p = (kt + r < Tk);
            long off = kbase + (long)(kt + r) * 128 + g * 8;
            uint32_t gs = ((uint32_t)g & 8u) | (((uint32_t)g & 7u) ^ ((uint32_t)r & 7u));
            uint32_t dst = sb + (uint32_t)r * 256u + (gs << 4);
            cp_async16(dst,          Kh + off, p);
            cp_async16(dst + 16384u, Kl + off, p);
            cp_async16(dst + 32768u, Vh + off, p);
            cp_async16(dst + 49152u, Vl + off, p);
        }
        CP_COMMIT();
        CP_WAIT0();
        __syncthreads();

        float s[8][4];
#pragma unroll
        for (int n = 0; n < 8; n++)
#pragma unroll
            for (int e = 0; e < 4; e++) s[n][e] = 0.f;

#pragma unroll
        for (int kc2 = 0; kc2 < 4; kc2++) {
#pragma unroll
            for (int nc = 0; nc < 8; nc++) {
                uint32_t row = (uint32_t)(nc * 8) + ln7;
                uint32_t g = (uint32_t)(kc2 * 4) + (uint32_t)(lane >> 3);
                uint32_t gs = (g & 8u) | ((g & 7u) ^ (row & 7u));
                uint32_t addr = sb + row * 256u + gs * 16u;
                uint32_t kh4[4], kl4[4];
                LDSM_X4(kh4, addr);
                LDSM_X4(kl4, addr + 16384u);
                MMA_BF16(s[nc], qh[2 * kc2],     &kh4[0]);
                MMA_BF16(s[nc], ql[2 * kc2],     &kh4[0]);
                MMA_BF16(s[nc], qh[2 * kc2],     &kl4[0]);
                MMA_BF16(s[nc], qh[2 * kc2 + 1], &kh4[2]);
                MMA_BF16(s[nc], ql[2 * kc2 + 1], &kh4[2]);
                MMA_BF16(s[nc], qh[2 * kc2 + 1], &kl4[2]);
            }
        }

#pragma unroll
        for (int nc = 0; nc < 8; nc++) {
#pragma unroll
            for (int e = 0; e < 4; e++) s[nc][e] *= ATT_SCALE;
        }

        if ((kt + 64 > Tk) || (causal && (kt + 63 >= qw))) {
#pragma unroll
            for (int nc = 0; nc < 8; nc++) {
#pragma unroll
                for (int e = 0; e < 4; e++) {
                    int kk = kt + nc * 8 + c2 + (e & 1);
                    int qr = qw + r0 + ((e >= 2) ? 8 : 0);
                    if (kk >= Tk || (causal && kk > qr)) s[nc][e] = -1e30f;
                }
            }
        }

        float mt0 = -1e30f, mt1 = -1e30f;
#pragma unroll
        for (int nc = 0; nc < 8; nc++) {
            mt0 = fmaxf(mt0, fmaxf(s[nc][0], s[nc][1]));
            mt1 = fmaxf(mt1, fmaxf(s[nc][2], s[nc][3]));
        }
        mt0 = fmaxf(mt0, __shfl_xor_sync(0xffffffffu, mt0, 1));
        mt0 = fmaxf(mt0, __shfl_xor_sync(0xffffffffu, mt0, 2));
        mt1 = fmaxf(mt1, __shfl_xor_sync(0xffffffffu, mt1, 1));
        mt1 = fmaxf(mt1, __shfl_xor_sync(0xffffffffu, mt1, 2));
        float mn0 = fmaxf(m0v, mt0), mn1 = fmaxf(m1v, mt1);
        float corr0 = __expf(m0v - mn0), corr1 = __expf(m1v - mn1);
        m0v = mn0; m1v = mn1;

        uint32_t ph[4][4], pl[4][4];
        float ps0 = 0.f, ps1 = 0.f;
#pragma unroll
        for (int nc = 0; nc < 8; nc++) {
            float p0 = __expf(s[nc][0] - mn0);
            float p1 = __expf(s[nc][1] - mn0);
            float p2 = __expf(s[nc][2] - mn1);
            float p3 = __expf(s[nc][3] - mn1);
            ps0 += p0 + p1; ps1 += p2 + p3;
            uint32_t h01, l01, h23, l23;
            split2(p0, p1, h01, l01);
            split2(p2, p3, h23, l23);
            int kc = nc >> 1;
            if ((nc & 1) == 0) { ph[kc][0] = h01; ph[kc][1] = h23; pl[kc][0] = l01; pl[kc][1] = l23; }
            else               { ph[kc][2] = h01; ph[kc][3] = h23; pl[kc][2] = l01; pl[kc][3] = l23; }
        }
        ps0 += __shfl_xor_sync(0xffffffffu, ps0, 1);
        ps0 += __shfl_xor_sync(0xffffffffu, ps0, 2);
        ps1 += __shfl_xor_sync(0xffffffffu, ps1, 1);
        ps1 += __shfl_xor_sync(0xffffffffu, ps1, 2);
        l0v = l0v * corr0 + ps0;
        l1v = l1v * corr1 + ps1;

#pragma unroll
        for (int n = 0; n < 16; n++) {
            o[n][0] *= corr0; o[n][1] *= corr0;
            o[n][2] *= corr1; o[n][3] *= corr1;
        }

#pragma unroll
        for (int kc = 0; kc < 4; kc++) {
            uint32_t row = (uint32_t)(kc * 16) + ((uint32_t)((lane >> 3) & 1)) * 8u + ln7;
#pragma unroll
            for (int dp = 0; dp < 8; dp++) {
                uint32_t g = (uint32_t)(dp * 2) + (uint32_t)(lane >> 4);
                uint32_t gs = (g & 8u) | ((g & 7u) ^ (row & 7u));
                uint32_t addr = sb + 32768u + row * 256u + gs * 16u;
                uint32_t vh4[4], vl4[4];
                LDSM_X4_T(vh4, addr);
                LDSM_X4_T(vl4, addr + 16384u);
                MMA_BF16(o[2 * dp],     ph[kc], &vh4[0]);
                MMA_BF16(o[2 * dp],     pl[kc], &vh4[0]);
                MMA_BF16(o[2 * dp],     ph[kc], &vl4[0]);
                MMA_BF16(o[2 * dp + 1], ph[kc], &vh4[2]);
                MMA_BF16(o[2 * dp + 1], pl[kc], &vh4[2]);
                MMA_BF16(o[2 * dp + 1], ph[kc], &vl4[2]);
            }
        }
    }

    float gate = gatep ? *gatep : 1.f;
    float sc0 = gate / l0v, sc1 = gate / l1v;
#pragma unroll
    for (int n = 0; n < 16; n++) {
        int gc = n * 8 + c2;
        long off0 = qbase + (long)(qw + r0) * 128 + gc;
        long off1 = off0 + 8 * 128;
        float2 v0 = make_float2(o[n][0] * sc0, o[n][1] * sc0);
        float2 v1 = make_float2(o[n][2] * sc1, o[n][3] * sc1);
        if (outmode >= 1) {
            float2 p0 = *(const float2*)&Out[off0];
            float2 p1 = *(const float2*)&Out[off1];
            v0.x += p0.x; v0.y += p0.y;
            v1.x += p1.x; v1.y += p1.y;
        }
        if (outmode == 2) {
            long offT0 = ((long)b * Tq + qw + r0) * (long)(H * 128) + (long)h * 128 + gc;
            long offT1 = offT0 + (long)8 * (H * 128);
            uint32_t hi, lo;
            split2(v0.x, v0.y, hi, lo);
            *(uint32_t*)&Oh[offT0] = hi;
            *(uint32_t*)&Ol[offT0] = lo;
            split2(v1.x, v1.y, hi, lo);
            *(uint32_t*)&Oh[offT1] = hi;
            *(uint32_t*)&Ol[offT1] = lo;
        } else {
            *(float2*)&Out[off0] = v0;
            *(float2*)&Out[off1] = v1;
        }
    }
}

// ================= rmsnorm per row -> bf16 planes =================
__global__ void rmsnorm_planes_kernel(const float* __restrict__ in, const float* __restrict__ w,
                                      __nv_bfloat16* __restrict__ oh, __nv_bfloat16* __restrict__ ol,
                                      int N)
{
    int row = blockIdx.x;
    const float* x = in + (long)row * N;
    float ss = 0.f;
    for (int c = threadIdx.x; c < N; c += 256) { float v = x[c]; ss = fmaf(v, v, ss); }
    __shared__ float sh[32];
    int lane = threadIdx.x & 31, wid = threadIdx.x >> 5;
#pragma unroll
    for (int o = 16; o; o >>= 1) ss += __shfl_xor_sync(0xffffffffu, ss, o);
    if (lane == 0) sh[wid] = ss;
    __syncthreads();
    float tot = (threadIdx.x < 8) ? sh[threadIdx.x] : 0.f;
    if (wid == 0) {
#pragma unroll
        for (int o = 16; o; o >>= 1) tot += __shfl_xor_sync(0xffffffffu, tot, o);
    }
    __shared__ float ssc;
    if (threadIdx.x == 0) ssc = rsqrtf(tot / (float)N + 1e-5f);
    __syncthreads();
    float sc = ssc;
    for (int c = threadIdx.x * 2; c < N; c += 512) {
        float v0 = x[c] * sc * w[c];
        float v1 = x[c + 1] * sc * w[c + 1];
        uint32_t hi, lo;
        split2(v0, v1, hi, lo);
        *(uint32_t*)&oh[(long)row * N + c] = hi;
        *(uint32_t*)&ol[(long)row * N + c] = lo;
    }
}

// ===== split qkv + rope -> q/k/v planes =====
__global__ void split_rope_kernel(const float* __restrict__ qkv,
                                  const float* __restrict__ cos_, const float* __restrict__ sin_,
                                  __nv_bfloat16* __restrict__ qh, __nv_bfloat16* __restrict__ qlp,
                                  __nv_bfloat16* __restrict__ kh, __nv_bfloat16* __restrict__ kl,
                                  __nv_bfloat16* __restrict__ vh, __nv_bfloat16* __restrict__ vl)
{
    int idx = blockIdx.x * blockDim.x + threadIdx.x;
    if (idx >= BB * TT * NH * 64) return;
    int i = idx & 63;
    int h = (idx >> 6) & 31;
    int t = (idx >> 11) & 1023;
    int b = idx >> 21;
    long base = ((long)(b * TT + t)) * (3 * CC) + h * HS + 2 * i;
    float q0 = qkv[base],        q1 = qkv[base + 1];
    float k0 = qkv[base + CC],   k1 = qkv[base + CC + 1];
    float v0 = qkv[base + 2*CC], v1 = qkv[base + 2*CC + 1];
    float c = cos_[t * 64 + i], s = sin_[t * 64 + i];
    long ob = ((long)((b * NH + h) * TT + t)) * HS + 2 * i;
    uint32_t hi, lo;
    split2(q0 * c - q1 * s, q1 * c + q0 * s, hi, lo);
    *(uint32_t*)&qh[ob] = hi;
    *(uint32_t*)&qlp[ob] = lo;
    split2(k0 * c - k1 * s, k1 * c + k0 * s, hi, lo);
    *(uint32_t*)&kh[ob] = hi;
    *(uint32_t*)&kl[ob] = lo;
    split2(v0, v1, hi, lo);
    *(uint32_t*)&vh[ob] = hi;
    *(uint32_t*)&vl[ob] = lo;
}

// ================= adapter split -> planes (reads fused qkv rows) =========
__global__ void adapter_split_kernel(const float* __restrict__ aqkv,
                                     __nv_bfloat16* __restrict__ akh, __nv_bfloat16* __restrict__ akl,
                                     __nv_bfloat16* __restrict__ avh, __nv_bfloat16* __restrict__ avl)
{
    int idx2 = blockIdx.x * blockDim.x + threadIdx.x;
    if (idx2 >= NH * ALEN * HS / 2) return;
    int idx = idx2 * 2;
    int d = idx & 127;
    int a = (idx >> 7) % ALEN;
    int h = idx / (ALEN * HS);
    long src = (long)a * (3 * CC) + h * HS + d;
    uint32_t hi, lo;
    split2(aqkv[src + CC], aqkv[src + CC + 1], hi, lo);
    *(uint32_t*)&akh[idx] = hi;
    *(uint32_t*)&akl[idx] = lo;
    split2(aqkv[src + 2*CC], aqkv[src + 2*CC + 1], hi, lo);
    *(uint32_t*)&avh[idx] = hi;
    *(uint32_t*)&avl[idx] = lo;
}

// ================= assemble pk/pv -> planes =================
__global__ void fill_pkv_kernel(const float* __restrict__ wflat, const float* __restrict__ pad,
                                __nv_bfloat16* __restrict__ ph, __nv_bfloat16* __restrict__ pl)
{
    int idx2 = blockIdx.x * blockDim.x + threadIdx.x;
    if (idx2 >= BB * NH * AT * HS / 2) return;
    int idx = idx2 * 2;
    int d = idx & 127;
    int t = (idx >> 7) % AT;
    int h = (idx / (HS * AT)) & 31;
    int b = idx / (HS * AT * NH);
    float v0, v1;
    if (h < NWH && d < WHD) {
        long src = (long)b * (AT * AD) + h * (AT * WHD) + t * WHD + d;
        v0 = wflat[src]; v1 = wflat[src + 1];
    } else {
        long src = ((long)b * AT + t) * HS + d;
        v0 = pad[src]; v1 = pad[src + 1];
    }
    uint32_t hi, lo;
    split2(v0, v1, hi, lo);
    *(uint32_t*)&ph[idx] = hi;
    *(uint32_t*)&pl[idx] = lo;
}

// ================= head mix -> q2 planes =================
__global__ __launch_bounds__(256) void headmix_kernel(const float* __restrict__ q2a,
                                                      const float* __restrict__ w,
                                                      __nv_bfloat16* __restrict__ q2h,
                                                      __nv_bfloat16* __restrict__ q2l)
{
    int bt = blockIdx.x;
    int b = bt >> 10, t = bt & 1023;
    __shared__ float sm[NH * HS];
    __shared__ float ws[NH * NH];
    for (int i = threadIdx.x; i < NH * HS; i += 256) {
        int h = i >> 7, d = i & 127;
        sm[i] = q2a[(((long)(b * NH + h)) * TT + t) * HS + d];
    }
    for (int i = threadIdx.x; i < NH * NH; i += 256) ws[i] = w[i];
    __syncthreads();
    for (int i2 = threadIdx.x; i2 < NH * HS / 2; i2 += 256) {
        int i = i2 * 2;
        int g = i >> 7, d = i & 127;
        float acc0 = 0.f, acc1 = 0.f;
#pragma unroll
        for (int h = 0; h < NH; h++) {
            float wv = ws[h * NH + g];
            acc0 = fmaf(sm[h * HS + d],     wv, acc0);
            acc1 = fmaf(sm[h * HS + d + 1], wv, acc1);
        }
        long dst = (((long)(b * NH + g)) * TT + t) * HS + d;
        uint32_t hi, lo;
        split2(acc0, acc1, hi, lo);
        *(uint32_t*)&q2h[dst] = hi;
        *(uint32_t*)&q2l[dst] = lo;
    }
}

// ================= host launcher =================
static float* symp(const void* symbol)
{
    void* p = nullptr;
    cudaGetSymbolAddress(&p, symbol);
    return (float*)p;
}
static __nv_bfloat16* symb(const void* symbol)
{
    void* p = nullptr;
    cudaGetSymbolAddress(&p, symbol);
    return (__nv_bfloat16*)p;
}

static inline void gemm_pl(const __nv_bfloat16* Ah, const __nv_bfloat16* Al,
                           const __nv_bfloat16* Bh, const __nv_bfloat16* Bl,
                           float* C, __nv_bfloat16* Ch, __nv_bfloat16* Cl,
                           int M, int N, int K, const float* bias, int mode)
{
    dim3 grid((M + 127) / 128, (N + 63) / 64);
    gemm_planes_kernel<<<grid, 128, GEMM_SMEM_BYTES>>>(Ah, Al, Bh, Bl, C, Ch, Cl, M, N, K, bias, mode);
}

static inline void convert(const float* in, __nv_bfloat16* h, __nv_bfloat16* l, long n)
{
    int n8 = (int)(n / 8);
    convert_kernel<<<(n8 + 255) / 256, 256>>>(in, h, l, n8);
}

extern "C" void kernel_launch(void* const* d_in, const int* in_sizes, int n_in,
                              void* d_out, int out_size)
{
    (void)in_sizes; (void)n_in; (void)out_size;
    const float* x        = (const float*)d_in[0];
    const float* audio    = (const float*)d_in[1];
    const float* rope_cos = (const float*)d_in[2];
    const float* rope_sin = (const float*)d_in[3];
    const float* pad_k    = (const float*)d_in[6];
    const float* pad_v    = (const float*)d_in[7];
    const float* c_attn_w = (const float*)d_in[8];
    const float* c_proj_w = (const float*)d_in[9];
    const float* adapter  = (const float*)d_in[10];
    const float* gating   = (const float*)d_in[11];
    const float* rms_gate = (const float*)d_in[12];
    const float* rms_key  = (const float*)d_in[13];
    const float* rms_val  = (const float*)d_in[14];
    const float* proj_dn  = (const float*)d_in[15];
    const float* proj_up  = (const float*)d_in[16];
    const float* pq128    = (const float*)d_in[17];
    const float* pq32     = (const float*)d_in[18];
    const float* pgating  = (const float*)d_in[19];
    const float* wkw      = (const float*)d_in[20];
    const float* wvw      = (const float*)d_in[21];
    const float* wvb      = (const float*)d_in[22];
    float* out = (float*)d_out;

    float *qkv = symp(g_qkv), *y = symp(g_y);
    float *wkn = symp(g_wkn), *wvn = symp(g_wvn), *wk = symp(g_wk), *wv = symp(g_wv);
    float *q2a = symp(g_q2a);

    __nv_bfloat16 *xh = symb(g_xh), *xl = symb(g_xl);
    __nv_bfloat16 *awh = symb(g_awh), *awl = symb(g_awl);
    __nv_bfloat16 *pwh = symb(g_pwh), *pwl = symb(g_pwl);
    __nv_bfloat16 *audh = symb(g_audh), *audl = symb(g_audl);
    __nv_bfloat16 *wkwh = symb(g_wkwh), *wkwl = symb(g_wkwl);
    __nv_bfloat16 *wvwh = symb(g_wvwh), *wvwl = symb(g_wvwl);
    __nv_bfloat16 *pdnh = symb(g_pdnh), *pdnl = symb(g_pdnl);
    __nv_bfloat16 *puph = symb(g_puph), *pupl = symb(g_pupl);
    __nv_bfloat16 *pqh = symb(g_pqh), *pql = symb(g_pql);
    __nv_bfloat16 *qph = symb(g_qph), *qpl = symb(g_qpl);
    __nv_bfloat16 *q2h = symb(g_q2h), *q2l = symb(g_q2l);
    __nv_bfloat16 *wknh = symb(g_wknh), *wknl = symb(g_wknl);
    __nv_bfloat16 *wvnh = symb(g_wvnh), *wvnl = symb(g_wvnl);
    __nv_bfloat16 *hidh = symb(g_hidh), *hidl = symb(g_hidl);
    __nv_bfloat16 *ybth = symb(g_ybth), *ybtl = symb(g_ybtl);
    __nv_bfloat16 *kh = symb(g_kh), *kl = symb(g_kl), *vh = symb(g_vh), *vl = symb(g_vl);
    __nv_bfloat16 *akh = symb(g_akh), *akl = symb(g_akl), *avh = symb(g_avh), *avl = symb(g_avl);
    __nv_bfloat16 *pkh = symb(g_pkh), *pkl = symb(g_pkl), *pvh = symb(g_pvh), *pvl = symb(g_pvl);

    cudaFuncSetAttribute(gemm_planes_kernel, cudaFuncAttributeMaxDynamicSharedMemorySize,
                         GEMM_SMEM_BYTES);
    cudaFuncSetAttribute(attn_mma_kernel, cudaFuncAttributeMaxDynamicSharedMemorySize,
                         ATTN_SMEM_BYTES);

    const int MA = BB * AT;           // 3000

    // 0) operand conversions; adapter rmsnorm planes appended to x planes
    convert(x, xh, xl, (long)BB*TT*CC);
    rmsnorm_planes_kernel<<<ALEN, 256>>>(adapter, rms_gate,
                                         xh + (long)BB*TT*CC, xl + (long)BB*TT*CC, CC);
    convert(c_attn_w, awh, awl, (long)CC*3*CC);
    convert(c_proj_w, pwh, pwl, (long)CC*CC);
    convert(audio, audh, audl, (long)BB*AT*AD);
    convert(wkw, wkwh, wkwl, (long)AD*AD);
    convert(wvw, wvwh, wvwl, (long)AD*AD);
    convert(proj_dn, pdnh, pdnl, (long)AD*DHID);
    convert(proj_up, puph, pupl, (long)DHID*AD);
    convert(pq128, pqh, pql, (long)HS*HS);

    // 1) fused qkv GEMM: [x; rms(adapter)] @ c_attn_w  (M = 2058)
    gemm_pl(xh, xl, awh, awl, qkv, nullptr, nullptr, MFUSE, 3*CC, CC, nullptr, 0);

    // 2) split + rope -> q/k/v planes (rows 0..2047); adapter split (rows 2048..2057)
    {
        int tot = BB * TT * NH * 64;
        split_rope_kernel<<<(tot + 255) / 256, 256>>>(qkv, rope_cos, rope_sin,
                                                      qph, qpl, kh, kl, vh, vl);
    }
    adapter_split_kernel<<<(NH*ALEN*HS/2 + 255) / 256, 256>>>(
        qkv + (long)BB*TT*3*CC, akh, akl, avh, avl);

    // 3) causal self-attention -> y
    attn_mma_kernel<<<dim3(TT/64, NH, BB), 128, ATTN_SMEM_BYTES>>>(
        qph, qpl, kh, kl, vh, vl, y, nullptr, nullptr,
        NH, TT, TT, (long)NH*TT*HS, (long)TT*HS, 1, nullptr, 0);

    // 4) adapter attention -> y += gating * ay
    attn_mma_kernel<<<dim3(TT/64, NH, BB), 128, ATTN_SMEM_BYTES>>>(
        qph, qpl, akh, akl, avh, avl, y, nullptr, nullptr,
        NH, TT, ALEN, 0L, (long)ALEN*HS, 0, gating, 1);

    // 5) whisper key path
    gemm_pl(audh, audl, wkwh, wkwl, wkn, nullptr, nullptr, MA, AD, AD, nullptr, 0);
    rmsnorm_planes_kernel<<<MA, 256>>>(wkn, rms_key, wknh, wknl, AD);
    gemm_pl(wknh, wknl, pdnh, pdnl, nullptr, hidh, hidl, MA, DHID, AD, nullptr, 3);
    gemm_pl(hidh, hidl, puph, pupl, wk, nullptr, nullptr, MA, AD, DHID, nullptr, 0);

    // 6) whisper value path
    gemm_pl(audh, audl, wvwh, wvwl, wvn, nullptr, nullptr, MA, AD, AD, wvb, 0);
    rmsnorm_planes_kernel<<<MA, 256>>>(wvn, rms_val, wvnh, wvnl, AD);
    gemm_pl(wvnh, wvnl, pdnh, pdnl, nullptr, hidh, hidl, MA, DHID, AD, nullptr, 3);
    gemm_pl(hidh, hidl, puph, pupl, wv, nullptr, nullptr, MA, AD, DHID, nullptr, 0);

    // 7) assemble pk/pv planes
    {
        int tot2 = BB * NH * AT * HS / 2;
        fill_pkv_kernel<<<(tot2 + 255) / 256, 256>>>(wk, pad_k, pkh, pkl);
        fill_pkv_kernel<<<(tot2 + 255) / 256, 256>>>(wv, pad_v, pvh, pvl);
    }

    // 8) q2 = (q @ proj_q128) head-mixed by proj_q32 -> planes
    gemm_pl(qph, qpl, pqh, pql, q2a, nullptr, nullptr, BB*NH*TT, HS, HS, nullptr, 0);
    headmix_kernel<<<BB * TT, 256>>>(q2a, pq32, q2h, q2l);

    // 9) whisper cross-attention -> fused accumulate + transpose -> ybt planes
    attn_mma_kernel<<<dim3(TT/64, NH, BB), 128, ATTN_SMEM_BYTES>>>(
        q2h, q2l, pkh, pkl, pvh, pvl, y, ybth, ybtl,
        NH, TT, AT, (long)NH*AT*HS, (long)AT*HS, 0, pgating, 2);

    // 10) output projection
    gemm_pl(ybth, ybtl, pwh, pwl, out, nullptr, nullptr, BB*TT, CC, CC, nullptr, 0);
}

// round 16
// speedup vs baseline: 1.0507x; 1.0128x over previous
#include <cuda_runtime.h>
#include <cuda_bf16.h>
#include <math.h>
#include <stdint.h>

// ---------------- problem constants ----------------
#define BB 2
#define TT 1024
#define CC 4096
#define NH 32
#define HS 128
#define ALEN 10
#define AT 1500
#define AD 1280
#define NWH 20
#define WHD 64
#define DHID 80           // AD/16
#define ATT_SCALE 0.08838834764831845f   // 1/sqrt(128)
#define MFUSE (BB*TT + ALEN)             // 2058: x rows + adapter rows

// ---------------- fp32 scratch ----------------
__device__ float g_qkv [(long)MFUSE*3*CC];
__device__ float g_y   [BB*NH*TT*HS];
__device__ float g_wkn [BB*AT*AD];
__device__ float g_wvn [BB*AT*AD];
__device__ float g_wkv [2L*BB*AT*AD];    // merged up-proj output: [K-path rows; V-path rows]
__device__ float g_q2a [BB*NH*TT*HS];

// ---------------- bf16 hi/lo plane scratch ----------------
__device__ __nv_bfloat16 g_xh[(long)MFUSE*CC], g_xl[(long)MFUSE*CC];
__device__ __nv_bfloat16 g_awh[CC*3*CC],    g_awl[CC*3*CC];
__device__ __nv_bfloat16 g_pwh[CC*CC],      g_pwl[CC*CC];
__device__ __nv_bfloat16 g_audh[BB*AT*AD],  g_audl[BB*AT*AD];
__device__ __nv_bfloat16 g_wkwh[AD*AD],     g_wkwl[AD*AD];
__device__ __nv_bfloat16 g_wvwh[AD*AD],     g_wvwl[AD*AD];
__device__ __nv_bfloat16 g_pdnh[AD*DHID],   g_pdnl[AD*DHID];
__device__ __nv_bfloat16 g_puph[DHID*AD],   g_pupl[DHID*AD];
__device__ __nv_bfloat16 g_pqh[HS*HS],      g_pql[HS*HS];
__device__ __nv_bfloat16 g_qph[BB*NH*TT*HS],g_qpl[BB*NH*TT*HS];
__device__ __nv_bfloat16 g_q2h[BB*NH*TT*HS],g_q2l[BB*NH*TT*HS];
__device__ __nv_bfloat16 g_wkvnh[2L*BB*AT*AD], g_wkvnl[2L*BB*AT*AD];   // merged rmsnorm planes
__device__ __nv_bfloat16 g_hidh[2L*BB*AT*DHID],g_hidl[2L*BB*AT*DHID];  // merged hidden planes
__device__ __nv_bfloat16 g_ybth[BB*TT*CC],  g_ybtl[BB*TT*CC];
// attention K/V planes
__device__ __nv_bfloat16 g_kh[BB*NH*TT*HS], g_kl[BB*NH*TT*HS];
__device__ __nv_bfloat16 g_vh[BB*NH*TT*HS], g_vl[BB*NH*TT*HS];
__device__ __nv_bfloat16 g_akh[NH*ALEN*HS], g_akl[NH*ALEN*HS];
__device__ __nv_bfloat16 g_avh[NH*ALEN*HS], g_avl[NH*ALEN*HS];
__device__ __nv_bfloat16 g_pkh[BB*NH*AT*HS],g_pkl[BB*NH*AT*HS];
__device__ __nv_bfloat16 g_pvh[BB*NH*AT*HS],g_pvl[BB*NH*AT*HS];

// ================= helpers =================
__device__ __forceinline__ uint32_t smem_u32(const void* p) {
    uint32_t a;
    asm("{ .reg .u64 t; cvta.to.shared.u64 t, %1; cvt.u32.u64 %0, t; }" : "=r"(a) : "l"(p));
    return a;
}

#define LDSM_X4(r, addr) \
    asm volatile("ldmatrix.sync.aligned.m8n8.x4.shared.b16 {%0,%1,%2,%3}, [%4];" \
        : "=r"((r)[0]), "=r"((r)[1]), "=r"((r)[2]), "=r"((r)[3]) : "r"(addr))
#define LDSM_X4_T(r, addr) \
    asm volatile("ldmatrix.sync.aligned.m8n8.x4.trans.shared.b16 {%0,%1,%2,%3}, [%4];" \
        : "=r"((r)[0]), "=r"((r)[1]), "=r"((r)[2]), "=r"((r)[3]) : "r"(addr))
#define MMA_BF16(c, a, b) \
    asm volatile("mma.sync.aligned.m16n8k16.row.col.f32.bf16.bf16.f32 " \
        "{%0,%1,%2,%3}, {%4,%5,%6,%7}, {%8,%9}, {%0,%1,%2,%3};" \
        : "+f"((c)[0]), "+f"((c)[1]), "+f"((c)[2]), "+f"((c)[3]) \
        : "r"((a)[0]), "r"((a)[1]), "r"((a)[2]), "r"((a)[3]), "r"((b)[0]), "r"((b)[1]))

__device__ __forceinline__ void cp_async16(uint32_t dst, const void* src, bool pred) {
    int sz = pred ? 16 : 0;
    asm volatile("cp.async.cg.shared.global [%0], [%1], 16, %2;"
                 :: "r"(dst), "l"(src), "r"(sz) : "memory");
}
#define CP_COMMIT() asm volatile("cp.async.commit_group;" ::: "memory")
#define CP_WAIT1()  asm volatile("cp.async.wait_group 1;"  ::: "memory")
#define CP_WAIT0()  asm volatile("cp.async.wait_group 0;"  ::: "memory")

__device__ __forceinline__ uint32_t pack_bf2(float a, float b) {
    __nv_bfloat162 t = __floats2bfloat162_rn(a, b);
    return *(uint32_t*)&t;
}
__device__ __forceinline__ void trunc_split4(const float4 v, uint2& hi, uint2& lo) {
    uint32_t x = __float_as_uint(v.x), y = __float_as_uint(v.y);
    uint32_t z = __float_as_uint(v.z), w = __float_as_uint(v.w);
    hi.x = __byte_perm(x, y, 0x7632);
    hi.y = __byte_perm(z, w, 0x7632);
    float r0 = v.x - __uint_as_float(x & 0xffff0000u);
    float r1 = v.y - __uint_as_float(y & 0xffff0000u);
    float r2 = v.z - __uint_as_float(z & 0xffff0000u);
    float r3 = v.w - __uint_as_float(w & 0xffff0000u);
    lo.x = pack_bf2(r0, r1);
    lo.y = pack_bf2(r2, r3);
}
__device__ __forceinline__ void split2(float a, float b, uint32_t& hi, uint32_t& lo) {
    uint32_t ua = __float_as_uint(a), ub = __float_as_uint(b);
    hi = __byte_perm(ua, ub, 0x7632);
    float ra = a - __uint_as_float(ua & 0xffff0000u);
    float rb = b - __uint_as_float(ub & 0xffff0000u);
    lo = pack_bf2(ra, rb);
}

// ======== fp32 -> bf16 plane converter ========
__global__ void convert_kernel(const float* __restrict__ in,
                               __nv_bfloat16* __restrict__ h, __nv_bfloat16* __restrict__ l,
                               int n8)
{
    int i = blockIdx.x * blockDim.x + threadIdx.x;
    if (i >= n8) return;
    float4 a = ((const float4*)in)[i * 2];
    float4 b = ((const float4*)in)[i * 2 + 1];
    uint2 h0, l0, h1, l1;
    trunc_split4(a, h0, l0);
    trunc_split4(b, h1, l1);
    uint4 H = make_uint4(h0.x, h0.y, h1.x, h1.y);
    uint4 L = make_uint4(l0.x, l0.y, l1.x, l1.y);
    ((uint4*)h)[i] = H;
    ((uint4*)l)[i] = L;
}

// ================= plane GEMM, 3 CTAs/SM =================
// mode: bit0 silu; bit1 write bf16 planes (Ch/Cl) instead of fp32 C.
#define NSTAGE 3
#define STAGE_BYTES 24576
#define GEMM_SMEM_BYTES (NSTAGE * STAGE_BYTES)

__global__ __launch_bounds__(128, 3) void gemm_planes_kernel(
    const __nv_bfloat16* __restrict__ Ah, const __nv_bfloat16* __restrict__ Al,
    const __nv_bfloat16* __restrict__ Bh, const __nv_bfloat16* __restrict__ Bl,
    float* __restrict__ C, __nv_bfloat16* __restrict__ Ch, __nv_bfloat16* __restrict__ Cl,
    int M, int N, int K, const float* __restrict__ bias, int mode)
{
    extern __shared__ __align__(128) unsigned char smem[];
    const uint32_t sbase = smem_u32(smem);
    const int tid = threadIdx.x;
    const int lane = tid & 31, warp = tid >> 5;
    const int wm = warp & 1, wn = warp >> 1;
    const int m0 = blockIdx.x * 128, n0 = blockIdx.y * 64;
    const int nkt = (K + 31) / 32;

    auto issue = [&](int t) {
        if (t < nkt) {
            uint32_t sB = sbase + (uint32_t)(t % NSTAGE) * STAGE_BYTES;
            int kt = t;
#pragma unroll
            for (int u = 0; u < 4; u++) {
                int idx = u * 128 + tid;
                int row = idx >> 2, g = idx & 3;
                int gk = kt * 32 + g * 8;
                bool p = (m0 + row < M) && (gk < K);
                long off = (long)(m0 + row) * K + gk;
                uint32_t dst = sB + (uint32_t)row * 64u + (uint32_t)((g ^ ((row >> 1) & 3)) << 4);
                cp_async16(dst,         Ah + off, p);
                cp_async16(dst + 8192u, Al + off, p);
            }
#pragma unroll
            for (int u = 0; u < 2; u++) {
                int idx = u * 128 + tid;
                int row = idx >> 3, g = idx & 7;
                int gk = kt * 32 + row;
                int gn = n0 + g * 8;
                bool p = (gk < K) && (gn < N);
                long off = (long)gk * N + gn;
                uint32_t gs = (uint32_t)g ^ ((uint32_t)row & 7u);
                uint32_t dst = sB + 16384u + (uint32_t)row * 128u + (gs << 4);
                cp_async16(dst,         Bh + off, p);
                cp_async16(dst + 4096u, Bl + off, p);
            }
        }
        CP_COMMIT();
    };

    float acc[4][4][4];
#pragma unroll
    for (int i = 0; i < 4; i++)
#pragma unroll
        for (int j = 0; j < 4; j++)
#pragma unroll
            for (int e = 0; e < 4; e++) acc[i][j][e] = 0.f;

    issue(0); issue(1);

    for (int t = 0; t < nkt; t++) {
        CP_WAIT1();
        __syncthreads();
        issue(t + 2);
        uint32_t aB = sbase + (uint32_t)(t % NSTAGE) * STAGE_BYTES;
        uint32_t bB = aB + 16384u;
#pragma unroll
        for (int ks = 0; ks < 2; ks++) {
            uint32_t ah[4][4], al[4][4], bh4[2][4], bl4[2][4];
#pragma unroll
            for (int i = 0; i < 4; i++) {
                uint32_t row = (uint32_t)(wm * 64 + i * 16 + (lane & 15));
                uint32_t lg = (uint32_t)(ks * 2) + ((uint32_t)lane >> 4);
                uint32_t addr = aB + row * 64u + ((lg ^ ((row >> 1) & 3u)) << 4);
                LDSM_X4(ah[i], addr);
                LDSM_X4(al[i], addr + 8192u);
            }
#pragma unroll
            for (int j2 = 0; j2 < 2; j2++) {
                uint32_t row = (uint32_t)(ks * 16) + (((uint32_t)lane >> 3) & 1u) * 8u + ((uint32_t)lane & 7u);
                uint32_t g = (uint32_t)(wn * 4 + j2 * 2) + ((uint32_t)lane >> 4);
                uint32_t gs = g ^ (row & 7u);
                uint32_t addr = bB + row * 128u + (gs << 4);
                LDSM_X4_T(bh4[j2], addr);
                LDSM_X4_T(bl4[j2], addr + 4096u);
            }
#pragma unroll
            for (int i = 0; i < 4; i++)
#pragma unroll
                for (int j = 0; j < 4; j++) {
                    uint32_t* bh = &bh4[j >> 1][(j & 1) * 2];
                    uint32_t* bl = &bl4[j >> 1][(j & 1) * 2];
                    MMA_BF16(acc[i][j], ah[i], bh);
                    MMA_BF16(acc[i][j], ah[i], bl);
                    MMA_BF16(acc[i][j], al[i], bh);
                }
        }
    }

#pragma unroll
    for (int i = 0; i < 4; i++) {
#pragma unroll
        for (int j = 0; j < 4; j++) {
            int gc = n0 + wn * 32 + j * 8 + (lane & 3) * 2;
            float b0v = 0.f, b1v = 0.f;
            if (bias && gc + 1 < N) { b0v = bias[gc]; b1v = bias[gc + 1]; }
#pragma unroll
            for (int half = 0; half < 2; half++) {
                int gr = m0 + wm * 64 + i * 16 + (lane >> 2) + half * 8;
                if (gr >= M || gc + 1 >= N) continue;
                float v0 = acc[i][j][half * 2 + 0] + b0v;
                float v1 = acc[i][j][half * 2 + 1] + b1v;
                if (mode & 1) {
                    v0 = v0 / (1.f + __expf(-v0));
                    v1 = v1 / (1.f + __expf(-v1));
                }
                long off = (long)gr * N + gc;
                if (mode & 2) {
                    uint32_t hi, lo;
                    split2(v0, v1, hi, lo);
                    *(uint32_t*)&Ch[off] = hi;
                    *(uint32_t*)&Cl[off] = lo;
                } else {
                    *(float2*)&C[off] = make_float2(v0, v1);
                }
            }
        }
    }
}

// ====== tensor-core flash attention: Q planes, bulk cp.async K/V ======
// outmode: 0 write fp32 Out; 1 accumulate into fp32 Out;
//          2 read fp32 Out, add, write transposed [B,T,C] bf16 planes Oh/Ol.
// causal launches process heavy q-tiles first (reversed blockIdx.x).
#define ATTN_SMEM_BYTES 65536

__global__ __launch_bounds__(128, 1) void attn_mma_kernel(
    const __nv_bfloat16* __restrict__ Qh, const __nv_bfloat16* __restrict__ Ql,
    const __nv_bfloat16* __restrict__ Kh, const __nv_bfloat16* __restrict__ Kl,
    const __nv_bfloat16* __restrict__ Vh, const __nv_bfloat16* __restrict__ Vl,
    float* __restrict__ Out, __nv_bfloat16* __restrict__ Oh, __nv_bfloat16* __restrict__ Ol,
    int H, int Tq, int Tk,
    long kvbs, long kvhs, int causal, const float* __restrict__ gatep, int outmode)
{
    extern __shared__ __align__(128) unsigned char smem[];
    const uint32_t sb = smem_u32(smem);
    const int tid = threadIdx.x, lane = tid & 31, warp = tid >> 5;
    const int qtile = causal ? (gridDim.x - 1 - blockIdx.x) : blockIdx.x;
    const int q0 = qtile * 64, h = blockIdx.y, b = blockIdx.z;
    const long qbase = ((long)(b * H + h)) * Tq * 128;
    const long kbase = (long)b * kvbs + (long)h * kvhs;
    const int qw = q0 + warp * 16;
    const int r0 = lane >> 2;
    const int c2 = (lane & 3) * 2;
    const uint32_t ln7 = lane & 7u;

    uint32_t qh[8][4], ql[8][4];
    {
        long ob0 = qbase + (long)(qw + r0) * 128;
        long ob1 = ob0 + 8 * 128;
#pragma unroll
        for (int kc = 0; kc < 8; kc++) {
            int cc0 = kc * 16 + c2, cc1 = kc * 16 + c2 + 8;
            qh[kc][0] = *(const uint32_t*)&Qh[ob0 + cc0];
            qh[kc][1] = *(const uint32_t*)&Qh[ob1 + cc0];
            qh[kc][2] = *(const uint32_t*)&Qh[ob0 + cc1];
            qh[kc][3] = *(const uint32_t*)&Qh[ob1 + cc1];
            ql[kc][0] = *(const uint32_t*)&Ql[ob0 + cc0];
            ql[kc][1] = *(const uint32_t*)&Ql[ob1 + cc0];
            ql[kc][2] = *(const uint32_t*)&Ql[ob0 + cc1];
            ql[kc][3] = *(const uint32_t*)&Ql[ob1 + cc1];
        }
    }

    float o[16][4];
#pragma unroll
    for (int n = 0; n < 16; n++)
#pragma unroll
        for (int e = 0; e < 4; e++) o[n][e] = 0.f;
    float m0v = -1e30f, m1v = -1e30f, l0v = 0.f, l1v = 0.f;

    const int kend = causal ? min(Tk, q0 + 64) : Tk;

    for (int kt = 0; kt < kend; kt += 64) {
        __syncthreads();
#pragma unroll
        for (int u = 0; u < 8; u++) {
            int idx = u * 128 + tid;
            int r = idx >> 4, g = idx & 15;
            bool p = (kt + r < Tk);
            long off = kbase + (long)(kt + r) * 128 + g * 8;
            uint32_t gs = ((uint32_t)g & 8u) | (((uint32_t)g & 7u) ^ ((uint32_t)r & 7u));
            uint32_t dst = sb + (uint32_t)r * 256u + (gs << 4);
            cp_async16(dst,          Kh + off, p);
            cp_async16(dst + 16384u, Kl + off, p);
            cp_async16(dst + 32768u, Vh + off, p);
            cp_async16(dst + 49152u, Vl + off, p);
        }
        CP_COMMIT();
        CP_WAIT0();
        __syncthreads();

        float s[8][4];
#pragma unroll
        for (int n = 0; n < 8; n++)
#pragma unroll
            for (int e = 0; e < 4; e++) s[n][e] = 0.f;

#pragma unroll
        for (int kc2 = 0; kc2 < 4; kc2++) {
#pragma unroll
            for (int nc = 0; nc < 8; nc++) {
                uint32_t row = (uint32_t)(nc * 8) + ln7;
                uint32_t g = (uint32_t)(kc2 * 4) + (uint32_t)(lane >> 3);
                uint32_t gs = (g & 8u) | ((g & 7u) ^ (row & 7u));
                uint32_t addr = sb + row * 256u + gs * 16u;
                uint32_t kh4[4], kl4[4];
                LDSM_X4(kh4, addr);
                LDSM_X4(kl4, addr + 16384u);
                MMA_BF16(s[nc], qh[2 * kc2],     &kh4[0]);
                MMA_BF16(s[nc], ql[2 * kc2],     &kh4[0]);
                MMA_BF16(s[nc], qh[2 * kc2],     &kl4[0]);
                MMA_BF16(s[nc], qh[2 * kc2 + 1], &kh4[2]);
                MMA_BF16(s[nc], ql[2 * kc2 + 1], &kh4[2]);
                MMA_BF16(s[nc], qh[2 * kc2 + 1], &kl4[2]);
            }
        }

#pragma unroll
        for (int nc = 0; nc < 8; nc++) {
#pragma unroll
            for (int e = 0; e < 4; e++) s[nc][e] *= ATT_SCALE;
        }

        if ((kt + 64 > Tk) || (causal && (kt + 63 >= qw))) {
#pragma unroll
            for (int nc = 0; nc < 8; nc++) {
#pragma unroll
                for (int e = 0; e < 4; e++) {
                    int kk = kt + nc * 8 + c2 + (e & 1);
                    int qr = qw + r0 + ((e >= 2) ? 8 : 0);
                    if (kk >= Tk || (causal && kk > qr)) s[nc][e] = -1e30f;
                }
            }
        }

        float mt0 = -1e30f, mt1 = -1e30f;
#pragma unroll
        for (int nc = 0; nc < 8; nc++) {
            mt0 = fmaxf(mt0, fmaxf(s[nc][0], s[nc][1]));
            mt1 = fmaxf(mt1, fmaxf(s[nc][2], s[nc][3]));
        }
        mt0 = fmaxf(mt0, __shfl_xor_sync(0xffffffffu, mt0, 1));
        mt0 = fmaxf(mt0, __shfl_xor_sync(0xffffffffu, mt0, 2));
        mt1 = fmaxf(mt1, __shfl_xor_sync(0xffffffffu, mt1, 1));
        mt1 = fmaxf(mt1, __shfl_xor_sync(0xffffffffu, mt1, 2));
        float mn0 = fmaxf(m0v, mt0), mn1 = fmaxf(m1v, mt1);
        float corr0 = __expf(m0v - mn0), corr1 = __expf(m1v - mn1);
        m0v = mn0; m1v = mn1;

        uint32_t ph[4][4], pl[4][4];
        float ps0 = 0.f, ps1 = 0.f;
#pragma unroll
        for (int nc = 0; nc < 8; nc++) {
            float p0 = __expf(s[nc][0] - mn0);
            float p1 = __expf(s[nc][1] - mn0);
            float p2 = __expf(s[nc][2] - mn1);
            float p3 = __expf(s[nc][3] - mn1);
            ps0 += p0 + p1; ps1 += p2 + p3;
            uint32_t h01, l01, h23, l23;
            split2(p0, p1, h01, l01);
            split2(p2, p3, h23, l23);
            int kc = nc >> 1;
            if ((nc & 1) == 0) { ph[kc][0] = h01; ph[kc][1] = h23; pl[kc][0] = l01; pl[kc][1] = l23; }
            else               { ph[kc][2] = h01; ph[kc][3] = h23; pl[kc][2] = l01; pl[kc][3] = l23; }
        }
        ps0 += __shfl_xor_sync(0xffffffffu, ps0, 1);
        ps0 += __shfl_xor_sync(0xffffffffu, ps0, 2);
        ps1 += __shfl_xor_sync(0xffffffffu, ps1, 1);
        ps1 += __shfl_xor_sync(0xffffffffu, ps1, 2);
        l0v = l0v * corr0 + ps0;
        l1v = l1v * corr1 + ps1;

#pragma unroll
        for (int n = 0; n < 16; n++) {
            o[n][0] *= corr0; o[n][1] *= corr0;
            o[n][2] *= corr1; o[n][3] *= corr1;
        }

#pragma unroll
        for (int kc = 0; kc < 4; kc++) {
            uint32_t row = (uint32_t)(kc * 16) + ((uint32_t)((lane >> 3) & 1)) * 8u + ln7;
#pragma unroll
            for (int dp = 0; dp < 8; dp++) {
                uint32_t g = (uint32_t)(dp * 2) + (uint32_t)(lane >> 4);
                uint32_t gs = (g & 8u) | ((g & 7u) ^ (row & 7u));
                uint32_t addr = sb + 32768u + row * 256u + gs * 16u;
                uint32_t vh4[4], vl4[4];
                LDSM_X4_T(vh4, addr);
                LDSM_X4_T(vl4, addr + 16384u);
                MMA_BF16(o[2 * dp],     ph[kc], &vh4[0]);
                MMA_BF16(o[2 * dp],     pl[kc], &vh4[0]);
                MMA_BF16(o[2 * dp],     ph[kc], &vl4[0]);
                MMA_BF16(o[2 * dp + 1], ph[kc], &vh4[2]);
                MMA_BF16(o[2 * dp + 1], pl[kc], &vh4[2]);
                MMA_BF16(o[2 * dp + 1], ph[kc], &vl4[2]);
            }
        }
    }

    float gate = gatep ? *gatep : 1.f;
    float sc0 = gate / l0v, sc1 = gate / l1v;
#pragma unroll
    for (int n = 0; n < 16; n++) {
        int gc = n * 8 + c2;
        long off0 = qbase + (long)(qw + r0) * 128 + gc;
        long off1 = off0 + 8 * 128;
        float2 v0 = make_float2(o[n][0] * sc0, o[n][1] * sc0);
        float2 v1 = make_float2(o[n][2] * sc1, o[n][3] * sc1);
        if (outmode >= 1) {
            float2 p0 = *(const float2*)&Out[off0];
            float2 p1 = *(const float2*)&Out[off1];
            v0.x += p0.x; v0.y += p0.y;
            v1.x += p1.x; v1.y += p1.y;
        }
        if (outmode == 2) {
            long offT0 = ((long)b * Tq + qw + r0) * (long)(H * 128) + (long)h * 128 + gc;
            long offT1 = offT0 + (long)8 * (H * 128);
            uint32_t hi, lo;
            split2(v0.x, v0.y, hi, lo);
            *(uint32_t*)&Oh[offT0] = hi;
            *(uint32_t*)&Ol[offT0] = lo;
            split2(v1.x, v1.y, hi, lo);
            *(uint32_t*)&Oh[offT1] = hi;
            *(uint32_t*)&Ol[offT1] = lo;
        } else {
            *(float2*)&Out[off0] = v0;
            *(float2*)&Out[off1] = v1;
        }
    }
}

// ================= rmsnorm per row -> bf16 planes =================
__global__ void rmsnorm_planes_kernel(const float* __restrict__ in, const float* __restrict__ w,
                                      __nv_bfloat16* __restrict__ oh, __nv_bfloat16* __restrict__ ol,
                                      int N)
{
    int row = blockIdx.x;
    const float* x = in + (long)row * N;
    float ss = 0.f;
    for (int c = threadIdx.x; c < N; c += 256) { float v = x[c]; ss = fmaf(v, v, ss); }
    __shared__ float sh[32];
    int lane = threadIdx.x & 31, wid = threadIdx.x >> 5;
#pragma unroll
    for (int o = 16; o; o >>= 1) ss += __shfl_xor_sync(0xffffffffu, ss, o);
    if (lane == 0) sh[wid] = ss;
    __syncthreads();
    float tot = (threadIdx.x < 8) ? sh[threadIdx.x] : 0.f;
    if (wid == 0) {
#pragma unroll
        for (int o = 16; o; o >>= 1) tot += __shfl_xor_sync(0xffffffffu, tot, o);
    }
    __shared__ float ssc;
    if (threadIdx.x == 0) ssc = rsqrtf(tot / (float)N + 1e-5f);
    __syncthreads();
    float sc = ssc;
    for (int c = threadIdx.x * 2; c < N; c += 512) {
        float v0 = x[c] * sc * w[c];
        float v1 = x[c + 1] * sc * w[c + 1];
        uint32_t hi, lo;
        split2(v0, v1, hi, lo);
        *(uint32_t*)&oh[(long)row * N + c] = hi;
        *(uint32_t*)&ol[(long)row * N + c] = lo;
    }
}

// ===== split qkv + rope -> q/k/v planes =====
__global__ void split_rope_kernel(const float* __restrict__ qkv,
                                  const float* __restrict__ cos_, const float* __restrict__ sin_,
                                  __nv_bfloat16* __restrict__ qh, __nv_bfloat16* __restrict__ qlp,
                                  __nv_bfloat16* __restrict__ kh, __nv_bfloat16* __restrict__ kl,
                                  __nv_bfloat16* __restrict__ vh, __nv_bfloat16* __restrict__ vl)
{
    int idx = blockIdx.x * blockDim.x + threadIdx.x;
    if (idx >= BB * TT * NH * 64) return;
    int i = idx & 63;
    int h = (idx >> 6) & 31;
    int t = (idx >> 11) & 1023;
    int b = idx >> 21;
    long base = ((long)(b * TT + t)) * (3 * CC) + h * HS + 2 * i;
    float q0 = qkv[base],        q1 = qkv[base + 1];
    float k0 = qkv[base + CC],   k1 = qkv[base + CC + 1];
    float v0 = qkv[base + 2*CC], v1 = qkv[base + 2*CC + 1];
    float c = cos_[t * 64 + i], s = sin_[t * 64 + i];
    long ob = ((long)((b * NH + h) * TT + t)) * HS + 2 * i;
    uint32_t hi, lo;
    split2(q0 * c - q1 * s, q1 * c + q0 * s, hi, lo);
    *(uint32_t*)&qh[ob] = hi;
    *(uint32_t*)&qlp[ob] = lo;
    split2(k0 * c - k1 * s, k1 * c + k0 * s, hi, lo);
    *(uint32_t*)&kh[ob] = hi;
    *(uint32_t*)&kl[ob] = lo;
    split2(v0, v1, hi, lo);
    *(uint32_t*)&vh[ob] = hi;
    *(uint32_t*)&vl[ob] = lo;
}

// ================= adapter split -> planes (reads fused qkv rows) =========
__global__ void adapter_split_kernel(const float* __restrict__ aqkv,
                                     __nv_bfloat16* __restrict__ akh, __nv_bfloat16* __restrict__ akl,
                                     __nv_bfloat16* __restrict__ avh, __nv_bfloat16* __restrict__ avl)
{
    int idx2 = blockIdx.x * blockDim.x + threadIdx.x;
    if (idx2 >= NH * ALEN * HS / 2) return;
    int idx = idx2 * 2;
    int d = idx & 127;
    int a = (idx >> 7) % ALEN;
    int h = idx / (ALEN * HS);
    long src = (long)a * (3 * CC) + h * HS + d;
    uint32_t hi, lo;
    split2(aqkv[src + CC], aqkv[src + CC + 1], hi, lo);
    *(uint32_t*)&akh[idx] = hi;
    *(uint32_t*)&akl[idx] = lo;
    split2(aqkv[src + 2*CC], aqkv[src + 2*CC + 1], hi, lo);
    *(uint32_t*)&avh[idx] = hi;
    *(uint32_t*)&avl[idx] = lo;
}

// ================= assemble pk/pv -> planes =================
__global__ void fill_pkv_kernel(const float* __restrict__ wflat, const float* __restrict__ pad,
                                __nv_bfloat16* __restrict__ ph, __nv_bfloat16* __restrict__ pl)
{
    int idx2 = blockIdx.x * blockDim.x + threadIdx.x;
    if (idx2 >= BB * NH * AT * HS / 2) return;
    int idx = idx2 * 2;
    int d = idx & 127;
    int t = (idx >> 7) % AT;
    int h = (idx / (HS * AT)) & 31;
    int b = idx / (HS * AT * NH);
    float v0, v1;
    if (h < NWH && d < WHD) {
        long src = (long)b * (AT * AD) + h * (AT * WHD) + t * WHD + d;
        v0 = wflat[src]; v1 = wflat[src + 1];
    } else {
        long src = ((long)b * AT + t) * HS + d;
        v0 = pad[src]; v1 = pad[src + 1];
    }
    uint32_t hi, lo;
    split2(v0, v1, hi, lo);
    *(uint32_t*)&ph[idx] = hi;
    *(uint32_t*)&pl[idx] = lo;
}

// ================= head mix -> q2 planes =================
__global__ __launch_bounds__(256) void headmix_kernel(const float* __restrict__ q2a,
                                                      const float* __restrict__ w,
                                                      __nv_bfloat16* __restrict__ q2h,
                                                      __nv_bfloat16* __restrict__ q2l)
{
    int bt = blockIdx.x;
    int b = bt >> 10, t = bt & 1023;
    __shared__ float sm[NH * HS];
    __shared__ float ws[NH * NH];
    for (int i = threadIdx.x; i < NH * HS; i += 256) {
        int h = i >> 7, d = i & 127;
        sm[i] = q2a[(((long)(b * NH + h)) * TT + t) * HS + d];
    }
    for (int i = threadIdx.x; i < NH * NH; i += 256) ws[i] = w[i];
    __syncthreads();
    for (int i2 = threadIdx.x; i2 < NH * HS / 2; i2 += 256) {
        int i = i2 * 2;
        int g = i >> 7, d = i & 127;
        float acc0 = 0.f, acc1 = 0.f;
#pragma unroll
        for (int h = 0; h < NH; h++) {
            float wv = ws[h * NH + g];
            acc0 = fmaf(sm[h * HS + d],     wv, acc0);
            acc1 = fmaf(sm[h * HS + d + 1], wv, acc1);
        }
        long dst = (((long)(b * NH + g)) * TT + t) * HS + d;
        uint32_t hi, lo;
        split2(acc0, acc1, hi, lo);
        *(uint32_t*)&q2h[dst] = hi;
        *(uint32_t*)&q2l[dst] = lo;
    }
}

// ================= host launcher =================
static float* symp(const void* symbol)
{
    void* p = nullptr;
    cudaGetSymbolAddress(&p, symbol);
    return (float*)p;
}
static __nv_bfloat16* symb(const void* symbol)
{
    void* p = nullptr;
    cudaGetSymbolAddress(&p, symbol);
    return (__nv_bfloat16*)p;
}

static inline void gemm_pl(const __nv_bfloat16* Ah, const __nv_bfloat16* Al,
                           const __nv_bfloat16* Bh, const __nv_bfloat16* Bl,
                           float* C, __nv_bfloat16* Ch, __nv_bfloat16* Cl,
                           int M, int N, int K, const float* bias, int mode)
{
    dim3 grid((M + 127) / 128, (N + 63) / 64);
    gemm_planes_kernel<<<grid, 128, GEMM_SMEM_BYTES>>>(Ah, Al, Bh, Bl, C, Ch, Cl, M, N, K, bias, mode);
}

static inline void convert(const float* in, __nv_bfloat16* h, __nv_bfloat16* l, long n)
{
    int n8 = (int)(n / 8);
    convert_kernel<<<(n8 + 255) / 256, 256>>>(in, h, l, n8);
}

extern "C" void kernel_launch(void* const* d_in, const int* in_sizes, int n_in,
                              void* d_out, int out_size)
{
    (void)in_sizes; (void)n_in; (void)out_size;
    const float* x        = (const float*)d_in[0];
    const float* audio    = (const float*)d_in[1];
    const float* rope_cos = (const float*)d_in[2];
    const float* rope_sin = (const float*)d_in[3];
    const float* pad_k    = (const float*)d_in[6];
    const float* pad_v    = (const float*)d_in[7];
    const float* c_attn_w = (const float*)d_in[8];
    const float* c_proj_w = (const float*)d_in[9];
    const float* adapter  = (const float*)d_in[10];
    const float* gating   = (const float*)d_in[11];
    const float* rms_gate = (const float*)d_in[12];
    const float* rms_key  = (const float*)d_in[13];
    const float* rms_val  = (const float*)d_in[14];
    const float* proj_dn  = (const float*)d_in[15];
    const float* proj_up  = (const float*)d_in[16];
    const float* pq128    = (const float*)d_in[17];
    const float* pq32     = (const float*)d_in[18];
    const float* pgating  = (const float*)d_in[19];
    const float* wkw      = (const float*)d_in[20];
    const float* wvw      = (const float*)d_in[21];
    const float* wvb      = (const float*)d_in[22];
    float* out = (float*)d_out;

    float *qkv = symp(g_qkv), *y = symp(g_y);
    float *wkn = symp(g_wkn), *wvn = symp(g_wvn), *wkv = symp(g_wkv);
    float *q2a = symp(g_q2a);

    __nv_bfloat16 *xh = symb(g_xh), *xl = symb(g_xl);
    __nv_bfloat16 *awh = symb(g_awh), *awl = symb(g_awl);
    __nv_bfloat16 *pwh = symb(g_pwh), *pwl = symb(g_pwl);
    __nv_bfloat16 *audh = symb(g_audh), *audl = symb(g_audl);
    __nv_bfloat16 *wkwh = symb(g_wkwh), *wkwl = symb(g_wkwl);
    __nv_bfloat16 *wvwh = symb(g_wvwh), *wvwl = symb(g_wvwl);
    __nv_bfloat16 *pdnh = symb(g_pdnh), *pdnl = symb(g_pdnl);
    __nv_bfloat16 *puph = symb(g_puph), *pupl = symb(g_pupl);
    __nv_bfloat16 *pqh = symb(g_pqh), *pql = symb(g_pql);
    __nv_bfloat16 *qph = symb(g_qph), *qpl = symb(g_qpl);
    __nv_bfloat16 *q2h = symb(g_q2h), *q2l = symb(g_q2l);
    __nv_bfloat16 *wkvnh = symb(g_wkvnh), *wkvnl = symb(g_wkvnl);
    __nv_bfloat16 *hidh = symb(g_hidh), *hidl = symb(g_hidl);
    __nv_bfloat16 *ybth = symb(g_ybth), *ybtl = symb(g_ybtl);
    __nv_bfloat16 *kh = symb(g_kh), *kl = symb(g_kl), *vh = symb(g_vh), *vl = symb(g_vl);
    __nv_bfloat16 *akh = symb(g_akh), *akl = symb(g_akl), *avh = symb(g_avh), *avl = symb(g_avl);
    __nv_bfloat16 *pkh = symb(g_pkh), *pkl = symb(g_pkl), *pvh = symb(g_pvh), *pvl = symb(g_pvl);

    cudaFuncSetAttribute(gemm_planes_kernel, cudaFuncAttributeMaxDynamicSharedMemorySize,
                         GEMM_SMEM_BYTES);
    cudaFuncSetAttribute(attn_mma_kernel, cudaFuncAttributeMaxDynamicSharedMemorySize,
                         ATTN_SMEM_BYTES);

    const int MA = BB * AT;           // 3000

    // 0) operand conversions; adapter rmsnorm planes appended to x planes
    convert(x, xh, xl, (long)BB*TT*CC);
    rmsnorm_planes_kernel<<<ALEN, 256>>>(adapter, rms_gate,
                                         xh + (long)BB*TT*CC, xl + (long)BB*TT*CC, CC);
    convert(c_attn_w, awh, awl, (long)CC*3*CC);
    convert(c_proj_w, pwh, pwl, (long)CC*CC);
    convert(audio, audh, audl, (long)BB*AT*AD);
    convert(wkw, wkwh, wkwl, (long)AD*AD);
    convert(wvw, wvwh, wvwl, (long)AD*AD);
    convert(proj_dn, pdnh, pdnl, (long)AD*DHID);
    convert(proj_up, puph, pupl, (long)DHID*AD);
    convert(pq128, pqh, pql, (long)HS*HS);

    // 1) fused qkv GEMM: [x; rms(adapter)] @ c_attn_w  (M = 2058)
    gemm_pl(xh, xl, awh, awl, qkv, nullptr, nullptr, MFUSE, 3*CC, CC, nullptr, 0);

    // 2) split + rope -> q/k/v planes; adapter split (rows 2048..2057)
    {
        int tot = BB * TT * NH * 64;
        split_rope_kernel<<<(tot + 255) / 256, 256>>>(qkv, rope_cos, rope_sin,
                                                      qph, qpl, kh, kl, vh, vl);
    }
    adapter_split_kernel<<<(NH*ALEN*HS/2 + 255) / 256, 256>>>(
        qkv + (long)BB*TT*3*CC, akh, akl, avh, avl);

    // 3) causal self-attention -> y (heavy q-tiles scheduled first)
    attn_mma_kernel<<<dim3(TT/64, NH, BB), 128, ATTN_SMEM_BYTES>>>(
        qph, qpl, kh, kl, vh, vl, y, nullptr, nullptr,
        NH, TT, TT, (long)NH*TT*HS, (long)TT*HS, 1, nullptr, 0);

    // 4) adapter attention -> y += gating * ay
    attn_mma_kernel<<<dim3(TT/64, NH, BB), 128, ATTN_SMEM_BYTES>>>(
        qph, qpl, akh, akl, avh, avl, y, nullptr, nullptr,
        NH, TT, ALEN, 0L, (long)ALEN*HS, 0, gating, 1);

    // 5) whisper K/V projections (separate GEMMs; share A)
    gemm_pl(audh, audl, wkwh, wkwl, wkn, nullptr, nullptr, MA, AD, AD, nullptr, 0);
    gemm_pl(audh, audl, wvwh, wvwl, wvn, nullptr, nullptr, MA, AD, AD, wvb, 0);

    // 6) rmsnorms -> merged plane buffer; merged dn + up GEMMs (M = 6000)
    rmsnorm_planes_kernel<<<MA, 256>>>(wkn, rms_key, wkvnh, wkvnl, AD);
    rmsnorm_planes_kernel<<<MA, 256>>>(wvn, rms_val,
                                       wkvnh + (long)MA*AD, wkvnl + (long)MA*AD, AD);
    gemm_pl(wkvnh, wkvnl, pdnh, pdnl, nullptr, hidh, hidl, 2*MA, DHID, AD, nullptr, 3);
    gemm_pl(hidh, hidl, puph, pupl, wkv, nullptr, nullptr, 2*MA, AD, DHID, nullptr, 0);

    // 7) assemble pk/pv planes from merged buffer
    {
        int tot2 = BB * NH * AT * HS / 2;
        fill_pkv_kernel<<<(tot2 + 255) / 256, 256>>>(wkv, pad_k, pkh, pkl);
        fill_pkv_kernel<<<(tot2 + 255) / 256, 256>>>(wkv + (long)MA*AD, pad_v, pvh, pvl);
    }

    // 8) q2 = (q @ proj_q128) head-mixed by proj_q32 -> planes
    gemm_pl(qph, qpl, pqh, pql, q2a, nullptr, nullptr, BB*NH*TT, HS, HS, nullptr, 0);
    headmix_kernel<<<BB * TT, 256>>>(q2a, pq32, q2h, q2l);

    // 9) whisper cross-attention -> fused accumulate + transpose -> ybt planes
    attn_mma_kernel<<<dim3(TT/64, NH, BB), 128, ATTN_SMEM_BYTES>>>(
        q2h, q2l, pkh, pkl, pvh, pvl, y, ybth, ybtl,
        NH, TT, AT, (long)NH*AT*HS, (long)AT*HS, 0, pgating, 2);

    // 10) output projection
    gemm_pl(ybth, ybtl, pwh, pwl, out, nullptr, nullptr, BB*TT, CC, CC, nullptr, 0);
}